// round 3
// baseline (speedup 1.0000x reference)
#include <cuda_runtime.h>
#include <cuda_bf16.h>
#include <math.h>

// Problem constants (fixed by the dataset)
#define NN 50000
#define EE 800000
#define INC 128
#define D1 256     // HID*HEADS
#define EMB 128

// ---------------- scratch (device globals; no allocation allowed) ------------
__device__ float g_q1[NN * D1];
__device__ float g_k1[NN * D1];
__device__ float g_v1[NN * D1];
__device__ float g_h [NN * D1];   // skip + attention out, then relu -> layer2 input
__device__ float g_q2[NN * EMB];
__device__ float g_k2[NN * EMB];
__device__ float g_v2[NN * EMB];
__device__ float g_o2[NN * EMB];  // layer2 skip + attention out

__device__ int g_deg   [NN];
__device__ int g_cursor[NN];
__device__ int g_incl  [NN];
__device__ int g_offs  [NN + 1];
__device__ int g_part  [128];
__device__ int g_cbase [128];
__device__ int g_srcs  [EE];
__device__ int g_is64;            // 1 if edge_index is int64, 0 if int32

// selector -> scratch buffer (device-side only; avoids cudaGetSymbolAddress)
__device__ __forceinline__ float* buf_ptr(int sel) {
    switch (sel) {
        case 0: return g_q1;
        case 1: return g_k1;
        case 2: return g_v1;
        case 3: return g_h;
        case 4: return g_q2;
        case 5: return g_k2;
        case 6: return g_v2;
        default: return g_o2;
    }
}

// read edge_index[idx] under detected dtype
__device__ __forceinline__ int edge_val(const void* ei, long long idx) {
    if (g_is64) return (int)((const long long*)ei)[idx];
    return ((const int*)ei)[idx];
}

// ---------------- dtype detection (reads only first 256 bytes) ---------------
__global__ void detect_kernel(const void* ei, int n) {
    if (threadIdx.x == 0 && blockIdx.x == 0) {
        const long long* p = (const long long*)ei;
        int ok = 1;
        for (int i = 0; i < 32; ++i) {
            long long v = p[i];
            if (v < 0 || v >= n) ok = 0;
        }
        g_is64 = ok;
    }
}

// ---------------- init: zero deg/cursor and output --------------------------
__global__ void init_kernel(float* out, int n) {
    int i = blockIdx.x * blockDim.x + threadIdx.x;
    if (i < n) { g_deg[i] = 0; g_cursor[i] = 0; }
    if (i < EMB) out[i] = 0.0f;
    if (i == 0) g_offs[0] = 0;
}

// ---------------- CSR build -------------------------------------------------
__global__ void hist_kernel(const void* __restrict__ ei, int e, int n) {
    int idx = blockIdx.x * blockDim.x + threadIdx.x;
    if (idx < e) {
        int d = edge_val(ei, (long long)e + idx);
        if (d >= 0 && d < n) atomicAdd(&g_deg[d], 1);
    }
}

// block-wise inclusive scan over chunks of 512
__global__ void scanA_kernel(int n) {
    __shared__ int s[512];
    int t = threadIdx.x;
    int i = blockIdx.x * 512 + t;
    int v = (i < n) ? g_deg[i] : 0;
    s[t] = v;
    __syncthreads();
    #pragma unroll
    for (int off = 1; off < 512; off <<= 1) {
        int add = (t >= off) ? s[t - off] : 0;
        __syncthreads();
        s[t] += add;
        __syncthreads();
    }
    if (i < n) g_incl[i] = s[t];
    if (t == 511) g_part[blockIdx.x] = s[511];
}

__global__ void scanB_kernel(int nchunks) {
    if (threadIdx.x == 0 && blockIdx.x == 0) {
        int run = 0;
        for (int b = 0; b < nchunks; ++b) {
            int t = g_part[b];
            g_cbase[b] = run;
            run += t;
        }
    }
}

__global__ void scanC_kernel(int n) {
    int i = blockIdx.x * blockDim.x + threadIdx.x;
    if (i < n) {
        g_offs[i + 1] = g_cbase[i >> 9] + g_incl[i];
    }
}

__global__ void scatter_kernel(const void* __restrict__ ei, int e, int n) {
    int idx = blockIdx.x * blockDim.x + threadIdx.x;
    if (idx < e) {
        int d = edge_val(ei, (long long)e + idx);
        int s = edge_val(ei, idx);
        if (d >= 0 && d < n && s >= 0 && s < n) {
            int pos = g_offs[d] + atomicAdd(&g_cursor[d], 1);
            g_srcs[pos] = s;
        }
    }
}

// ---------------- SGEMM: C[M,N] = A[M,K] @ B[K,N] + bias --------------------
// BM=128, BN=128, BK=8, 256 threads, 8x8 per thread. N, K multiples of 128/8.
// a_sel: 0 -> use Aext (external input), 1 -> use g_h. out_sel: scratch buffer.
__global__ __launch_bounds__(256) void sgemm_kernel(
    const float* __restrict__ Aext, int a_sel,
    const float* __restrict__ B,
    const float* __restrict__ bias, int out_sel,
    int M, int N, int K)
{
    __shared__ float As[8][128];
    __shared__ float Bs[8][128];

    const float* A = (a_sel == 0) ? Aext : (const float*)g_h;
    float* C = buf_ptr(out_sel);

    int tid = threadIdx.x;
    int tx = tid & 15;        // col group
    int ty = tid >> 4;        // row group
    int row0 = blockIdx.y * 128;
    int col0 = blockIdx.x * 128;

    int aRow = tid >> 1;
    int aCol = (tid & 1) * 4;
    int bRow = tid >> 5;
    int bCol = (tid & 31) * 4;

    const float* Aptr = A + (size_t)(row0 + aRow) * K + aCol;
    const float* Bptr = B + (size_t)bRow * N + col0 + bCol;
    bool aValid = (row0 + aRow) < M;

    float acc[8][8];
    #pragma unroll
    for (int i = 0; i < 8; ++i)
        #pragma unroll
        for (int j = 0; j < 8; ++j) acc[i][j] = 0.0f;

    for (int k0 = 0; k0 < K; k0 += 8) {
        float4 av = aValid ? *(const float4*)(Aptr + k0) : make_float4(0.f,0.f,0.f,0.f);
        As[aCol + 0][aRow] = av.x;
        As[aCol + 1][aRow] = av.y;
        As[aCol + 2][aRow] = av.z;
        As[aCol + 3][aRow] = av.w;
        float4 bv = *(const float4*)(Bptr + (size_t)k0 * N);
        *(float4*)&Bs[bRow][bCol] = bv;
        __syncthreads();
        #pragma unroll
        for (int k = 0; k < 8; ++k) {
            float ar[8], br[8];
            #pragma unroll
            for (int i = 0; i < 8; ++i) ar[i] = As[k][ty * 8 + i];
            #pragma unroll
            for (int j = 0; j < 8; ++j) br[j] = Bs[k][tx * 8 + j];
            #pragma unroll
            for (int i = 0; i < 8; ++i)
                #pragma unroll
                for (int j = 0; j < 8; ++j)
                    acc[i][j] += ar[i] * br[j];
        }
        __syncthreads();
    }

    int cb = col0 + tx * 8;
    #pragma unroll
    for (int i = 0; i < 8; ++i) {
        int r = row0 + ty * 8 + i;
        if (r < M) {
            float* crow = C + (size_t)r * N + cb;
            #pragma unroll
            for (int j = 0; j < 8; ++j)
                crow[j] = acc[i][j] + bias[cb + j];
        }
    }
}

// ---------------- attention layer 1: 4 heads, d=64, warp per (node,head) ----
// reads g_q1/g_k1/g_v1, adds into g_h
__global__ void attn1_kernel(int n)
{
    int gw = (blockIdx.x * blockDim.x + threadIdx.x) >> 5;
    int lane = threadIdx.x & 31;
    int node = gw >> 2;
    int head = gw & 3;
    if (node >= n) return;

    int base = node * D1 + head * 64;
    float2 qv = *(const float2*)(g_q1 + base + 2 * lane);

    float m = -1e30f, l = 0.0f, a0 = 0.0f, a1 = 0.0f;
    int beg = g_offs[node], end = g_offs[node + 1];
    for (int p = beg; p < end; ++p) {
        int s = g_srcs[p];
        int sb = s * D1 + head * 64 + 2 * lane;
        float2 kv = *(const float2*)(g_k1 + sb);
        float d = qv.x * kv.x + qv.y * kv.y;
        #pragma unroll
        for (int o = 16; o; o >>= 1) d += __shfl_xor_sync(0xffffffffu, d, o);
        float logit = d * 0.125f;          // 1/sqrt(64)
        float mn = fmaxf(m, logit);
        float c  = __expf(m - mn);
        float pe = __expf(logit - mn);
        l = l * c + pe;
        float2 vv = *(const float2*)(g_v1 + sb);
        a0 = a0 * c + pe * vv.x;
        a1 = a1 * c + pe * vv.y;
        m = mn;
    }
    if (l > 0.0f) {
        float inv = 1.0f / l;
        g_h[base + 2 * lane]     += a0 * inv;
        g_h[base + 2 * lane + 1] += a1 * inv;
    }
}

// ---------------- attention layer 2: 1 head, d=128, warp per node -----------
// reads g_q2/g_k2/g_v2, adds into g_o2
__global__ void attn2_kernel(int n)
{
    int node = (blockIdx.x * blockDim.x + threadIdx.x) >> 5;
    int lane = threadIdx.x & 31;
    if (node >= n) return;

    int base = node * EMB + 4 * lane;
    float4 qv = *(const float4*)(g_q2 + base);

    float m = -1e30f, l = 0.0f;
    float a0 = 0.f, a1 = 0.f, a2 = 0.f, a3 = 0.f;
    int beg = g_offs[node], end = g_offs[node + 1];
    const float scale = 0.088388347648318447f;   // 1/sqrt(128)
    for (int p = beg; p < end; ++p) {
        int s = g_srcs[p];
        int sb = s * EMB + 4 * lane;
        float4 kv = *(const float4*)(g_k2 + sb);
        float d = qv.x * kv.x + qv.y * kv.y + qv.z * kv.z + qv.w * kv.w;
        #pragma unroll
        for (int o = 16; o; o >>= 1) d += __shfl_xor_sync(0xffffffffu, d, o);
        float logit = d * scale;
        float mn = fmaxf(m, logit);
        float c  = __expf(m - mn);
        float pe = __expf(logit - mn);
        l = l * c + pe;
        float4 vv = *(const float4*)(g_v2 + sb);
        a0 = a0 * c + pe * vv.x;
        a1 = a1 * c + pe * vv.y;
        a2 = a2 * c + pe * vv.z;
        a3 = a3 * c + pe * vv.w;
        m = mn;
    }
    if (l > 0.0f) {
        float inv = 1.0f / l;
        g_o2[base + 0] += a0 * inv;
        g_o2[base + 1] += a1 * inv;
        g_o2[base + 2] += a2 * inv;
        g_o2[base + 3] += a3 * inv;
    }
}

// ---------------- relu in-place on g_h ---------------------------------------
__global__ void relu_kernel(int n) {
    int i = blockIdx.x * blockDim.x + threadIdx.x;
    int stride = gridDim.x * blockDim.x;
    for (; i < n; i += stride) g_h[i] = fmaxf(g_h[i], 0.0f);
}

// ---------------- final mean over nodes (reads g_o2) -------------------------
__global__ void reduce_mean_kernel(float* __restrict__ out, int n) {
    int col = threadIdx.x;   // 128 threads
    float s = 0.0f;
    for (int r = blockIdx.x; r < n; r += gridDim.x)
        s += g_o2[(size_t)r * EMB + col];
    atomicAdd(&out[col], s * (1.0f / (float)n));
}

// ---------------- launch -----------------------------------------------------
extern "C" void kernel_launch(void* const* d_in, const int* in_sizes, int n_in,
                              void* d_out, int out_size)
{
    const float* x  = (const float*)d_in[0];
    const void*  ei = d_in[1];
    const float *Wq1 = (const float*)d_in[2],  *bq1 = (const float*)d_in[3];
    const float *Wk1 = (const float*)d_in[4],  *bk1 = (const float*)d_in[5];
    const float *Wv1 = (const float*)d_in[6],  *bv1 = (const float*)d_in[7];
    const float *Ws1 = (const float*)d_in[8],  *bs1 = (const float*)d_in[9];
    const float *Wq2 = (const float*)d_in[10], *bq2 = (const float*)d_in[11];
    const float *Wk2 = (const float*)d_in[12], *bk2 = (const float*)d_in[13];
    const float *Wv2 = (const float*)d_in[14], *bv2 = (const float*)d_in[15];
    const float *Ws2 = (const float*)d_in[16], *bs2 = (const float*)d_in[17];
    float* out = (float*)d_out;

    const int n = in_sizes[0] / INC;   // 50000
    const int e = in_sizes[1] / 2;     // 800000

    // ---- edge dtype detection + CSR build (by dst) ----
    {
        int threads = 256;
        detect_kernel<<<1, 32>>>(ei, n);
        init_kernel<<<(n + threads - 1) / threads, threads>>>(out, n);
        hist_kernel<<<(e + threads - 1) / threads, threads>>>(ei, e, n);
        int nchunks = (n + 511) / 512;
        scanA_kernel<<<nchunks, 512>>>(n);
        scanB_kernel<<<1, 32>>>(nchunks);
        scanC_kernel<<<(n + threads - 1) / threads, threads>>>(n);
        scatter_kernel<<<(e + threads - 1) / threads, threads>>>(ei, e, n);
    }

    // ---- layer 1 projections ----
    {
        dim3 grid(D1 / 128, (n + 127) / 128);
        sgemm_kernel<<<grid, 256>>>(x, 0, Wq1, bq1, 0, n, D1, INC);  // -> g_q1
        sgemm_kernel<<<grid, 256>>>(x, 0, Wk1, bk1, 1, n, D1, INC);  // -> g_k1
        sgemm_kernel<<<grid, 256>>>(x, 0, Wv1, bv1, 2, n, D1, INC);  // -> g_v1
        sgemm_kernel<<<grid, 256>>>(x, 0, Ws1, bs1, 3, n, D1, INC);  // -> g_h (skip)
    }

    // ---- layer 1 attention (adds into g_h) + relu ----
    {
        int warps = n * 4;
        int blocks = (warps + 7) / 8;
        attn1_kernel<<<blocks, 256>>>(n);
        relu_kernel<<<592, 256>>>(n * D1);
    }

    // ---- layer 2 projections (A = g_h) ----
    {
        dim3 grid(EMB / 128, (n + 127) / 128);
        sgemm_kernel<<<grid, 256>>>(nullptr, 1, Wq2, bq2, 4, n, EMB, D1);  // -> g_q2
        sgemm_kernel<<<grid, 256>>>(nullptr, 1, Wk2, bk2, 5, n, EMB, D1);  // -> g_k2
        sgemm_kernel<<<grid, 256>>>(nullptr, 1, Wv2, bv2, 6, n, EMB, D1);  // -> g_v2
        sgemm_kernel<<<grid, 256>>>(nullptr, 1, Ws2, bs2, 7, n, EMB, D1);  // -> g_o2 (skip)
    }

    // ---- layer 2 attention (adds into g_o2) ----
    {
        int blocks = (n + 7) / 8;
        attn2_kernel<<<blocks, 256>>>(n);
    }

    // ---- final mean over nodes ----
    reduce_mean_kernel<<<256, EMB>>>(out, n);
}

// round 5
// speedup vs baseline: 1.7984x; 1.7984x over previous
#include <cuda_runtime.h>
#include <cuda_bf16.h>
#include <math.h>
#include <stdint.h>

// Problem constants (fixed by the dataset)
#define NN 50000
#define EE 800000
#define INC 128
#define D1 256     // HID*HEADS
#define EMB 128

// ---------------- scratch (device globals; no allocation allowed) ------------
__device__ float g_q1[NN * D1];
__device__ float g_k1[NN * D1];
__device__ float g_v1[NN * D1];
__device__ float g_h [NN * D1];   // skip + attention out (fp32)
__device__ float g_q2[NN * EMB];
__device__ float g_k2[NN * EMB];
__device__ float g_v2[NN * EMB];
__device__ float g_o2[NN * EMB];  // layer2 skip + attention out

// bf16 hi/lo splits for tensor-core GEMM inputs
__device__ __nv_bfloat16 g_xh[NN * INC];
__device__ __nv_bfloat16 g_xl[NN * INC];
__device__ __nv_bfloat16 g_hh[NN * D1];
__device__ __nv_bfloat16 g_hl[NN * D1];
// transposed+split weights: layer1 at [0, 131072) (4 mats * 256*128),
// layer2 at [131072, 262144) (4 mats * 128*256).  Layout: Wt[n][k] row-major.
__device__ __nv_bfloat16 g_wh[262144];
__device__ __nv_bfloat16 g_wl[262144];

__device__ int g_deg   [NN];
__device__ int g_cursor[NN];
__device__ int g_incl  [NN];
__device__ int g_offs  [NN + 1];
__device__ int g_part  [128];
__device__ int g_cbase [128];
__device__ int g_srcs  [EE];
__device__ int g_is64;            // 1 if edge_index is int64, 0 if int32

// selector -> scratch buffer (device-side only)
__device__ __forceinline__ float* buf_ptr(int sel) {
    switch (sel) {
        case 0: return g_q1;
        case 1: return g_k1;
        case 2: return g_v1;
        case 3: return g_h;
        case 4: return g_q2;
        case 5: return g_k2;
        case 6: return g_v2;
        default: return g_o2;
    }
}

// read edge_index[idx] under detected dtype
__device__ __forceinline__ int edge_val(const void* ei, long long idx) {
    if (g_is64) return (int)((const long long*)ei)[idx];
    return ((const int*)ei)[idx];
}

__device__ __forceinline__ uint32_t smem_u32(const void* p) {
    uint32_t a;
    asm("{ .reg .u64 t; cvta.to.shared.u64 t, %1; cvt.u32.u64 %0, t; }"
        : "=r"(a) : "l"(p));
    return a;
}

// ldmatrix x4 (b16, no transpose)
__device__ __forceinline__ void ldsm4(uint32_t* r, uint32_t addr) {
    asm volatile("ldmatrix.sync.aligned.m8n8.x4.shared.b16 {%0,%1,%2,%3}, [%4];"
                 : "=r"(r[0]), "=r"(r[1]), "=r"(r[2]), "=r"(r[3]) : "r"(addr));
}

// mma m16n8k16 bf16 -> fp32 accumulate
__device__ __forceinline__ void mma_bf16(float* d, const uint32_t* a,
                                         uint32_t b0, uint32_t b1) {
    asm volatile(
        "mma.sync.aligned.m16n8k16.row.col.f32.bf16.bf16.f32 "
        "{%0,%1,%2,%3}, {%4,%5,%6,%7}, {%8,%9}, {%0,%1,%2,%3};"
        : "+f"(d[0]), "+f"(d[1]), "+f"(d[2]), "+f"(d[3])
        : "r"(a[0]), "r"(a[1]), "r"(a[2]), "r"(a[3]), "r"(b0), "r"(b1));
}

// ---------------- dtype detection (reads only first 256 bytes) ---------------
__global__ void detect_kernel(const void* ei, int n) {
    if (threadIdx.x == 0 && blockIdx.x == 0) {
        const long long* p = (const long long*)ei;
        int ok = 1;
        for (int i = 0; i < 32; ++i) {
            long long v = p[i];
            if (v < 0 || v >= n) ok = 0;
        }
        g_is64 = ok;
    }
}

// ---------------- init: zero deg/cursor and output --------------------------
__global__ void init_kernel(float* out, int n) {
    int i = blockIdx.x * blockDim.x + threadIdx.x;
    if (i < n) { g_deg[i] = 0; g_cursor[i] = 0; }
    if (i < EMB) out[i] = 0.0f;
    if (i == 0) g_offs[0] = 0;
}

// ---------------- CSR build -------------------------------------------------
__global__ void hist_kernel(const void* __restrict__ ei, int e, int n) {
    int idx = blockIdx.x * blockDim.x + threadIdx.x;
    if (idx < e) {
        int d = edge_val(ei, (long long)e + idx);
        if (d >= 0 && d < n) atomicAdd(&g_deg[d], 1);
    }
}

__global__ void scanA_kernel(int n) {
    __shared__ int s[512];
    int t = threadIdx.x;
    int i = blockIdx.x * 512 + t;
    int v = (i < n) ? g_deg[i] : 0;
    s[t] = v;
    __syncthreads();
    #pragma unroll
    for (int off = 1; off < 512; off <<= 1) {
        int add = (t >= off) ? s[t - off] : 0;
        __syncthreads();
        s[t] += add;
        __syncthreads();
    }
    if (i < n) g_incl[i] = s[t];
    if (t == 511) g_part[blockIdx.x] = s[511];
}

__global__ void scanB_kernel(int nchunks) {
    if (threadIdx.x == 0 && blockIdx.x == 0) {
        int run = 0;
        for (int b = 0; b < nchunks; ++b) {
            int t = g_part[b];
            g_cbase[b] = run;
            run += t;
        }
    }
}

__global__ void scanC_kernel(int n) {
    int i = blockIdx.x * blockDim.x + threadIdx.x;
    if (i < n) g_offs[i + 1] = g_cbase[i >> 9] + g_incl[i];
}

__global__ void scatter_kernel(const void* __restrict__ ei, int e, int n) {
    int idx = blockIdx.x * blockDim.x + threadIdx.x;
    if (idx < e) {
        int d = edge_val(ei, (long long)e + idx);
        int s = edge_val(ei, idx);
        if (d >= 0 && d < n && s >= 0 && s < n) {
            int pos = g_offs[d] + atomicAdd(&g_cursor[d], 1);
            g_srcs[pos] = s;
        }
    }
}

// ---------------- bf16 split passes ------------------------------------------
__global__ void xsplit_kernel(const float* __restrict__ x, int total) {
    int i = blockIdx.x * blockDim.x + threadIdx.x;
    if (i < total) {
        float v = x[i];
        __nv_bfloat16 hi = __float2bfloat16(v);
        g_xh[i] = hi;
        g_xl[i] = __float2bfloat16(v - __bfloat162float(hi));
    }
}

// relu(g_h) -> (g_hh, g_hl)
__global__ void relu_split_kernel(int total) {
    int i = blockIdx.x * blockDim.x + threadIdx.x;
    int stride = gridDim.x * blockDim.x;
    for (; i < total; i += stride) {
        float v = fmaxf(g_h[i], 0.0f);
        __nv_bfloat16 hi = __float2bfloat16(v);
        g_hh[i] = hi;
        g_hl[i] = __float2bfloat16(v - __bfloat162float(hi));
    }
}

// transpose + split all 8 weight matrices into g_wh/g_wl
__global__ void wsplit_kernel(const float* w0, const float* w1, const float* w2, const float* w3,
                              const float* w4, const float* w5, const float* w6, const float* w7) {
    int tid = blockIdx.x * blockDim.x + threadIdx.x;
    if (tid >= 262144) return;
    float v;
    int idx;
    if (tid < 131072) {
        int m = tid >> 15, r = tid & 32767;
        int n = r >> 7, k = r & 127;
        const float* W = (m == 0) ? w0 : (m == 1) ? w1 : (m == 2) ? w2 : w3;
        v = W[k * 256 + n];
        idx = m * 32768 + n * 128 + k;
    } else {
        int e = tid - 131072;
        int m = e >> 15, r = e & 32767;
        int n = r >> 8, k = r & 255;
        const float* W = (m == 0) ? w4 : (m == 1) ? w5 : (m == 2) ? w6 : w7;
        v = W[k * 128 + n];
        idx = 131072 + m * 32768 + n * 256 + k;
    }
    __nv_bfloat16 hi = __float2bfloat16(v);
    g_wh[idx] = hi;
    g_wl[idx] = __float2bfloat16(v - __bfloat162float(hi));
}

// ---------------- mma.sync GEMM -----------------------------------------------
// C[M,Ntot] 128x128 block tile; A[M,K] bf16 hi/lo, B = Wt[N][K] bf16 hi/lo.
// 3-term: Ah*Bh + Ah*Bl + Al*Bh, fp32 accum. 8 warps = 4(m) x 2(n); warp: 32m x 64n.
#define BK 32
#define LDT 40   // smem row stride in bf16 elems (80 B, 16B-aligned, conflict-free)

__global__ __launch_bounds__(256, 2)
void mma_gemm_kernel(const float* __restrict__ b0, const float* __restrict__ b1,
                     const float* __restrict__ b2, const float* __restrict__ b3,
                     int M, int K, int ntiles, int wt_base, int layer, int out_base)
{
    __shared__ __nv_bfloat16 sAh[128 * LDT];
    __shared__ __nv_bfloat16 sAl[128 * LDT];
    __shared__ __nv_bfloat16 sBh[128 * LDT];
    __shared__ __nv_bfloat16 sBl[128 * LDT];

    int tid = threadIdx.x, wid = tid >> 5, lane = tid & 31;
    int mat = blockIdx.x / ntiles, nt0 = blockIdx.x % ntiles;
    int m0 = blockIdx.y * 128;
    int n0 = nt0 * 128;
    int Ntot = ntiles * 128;

    const __nv_bfloat16* Ah = layer ? g_hh : g_xh;
    const __nv_bfloat16* Al = layer ? g_hl : g_xl;
    const __nv_bfloat16* Bh = g_wh + wt_base + mat * 32768;
    const __nv_bfloat16* Bl = g_wl + wt_base + mat * 32768;
    float* C = buf_ptr(out_base + mat);
    const float* bias = (mat == 0) ? b0 : (mat == 1) ? b1 : (mat == 2) ? b2 : b3;

    int warp_m = wid >> 1;       // 0..3  -> rows warp_m*32
    int warp_n = wid & 1;        // 0..1  -> cols warp_n*64

    float acc[2][8][4];
    #pragma unroll
    for (int i = 0; i < 2; ++i)
        #pragma unroll
        for (int j = 0; j < 8; ++j)
            #pragma unroll
            for (int q = 0; q < 4; ++q) acc[i][j][q] = 0.0f;

    // ldmatrix source addresses (fixed per thread per tile)
    // A: row = warpm*32 + mt*16 + (lane&15), kcol = kstep*16 + (lane>>4)*8
    uint32_t a_row = warp_m * 32 + (lane & 15);
    uint32_t a_koff = (lane >> 4) * 8;
    // B: nrow = warpn*64 + nb*16 + (lane&7) + ((lane>>3)&1)*8, kcol same pattern
    uint32_t b_nrow = warp_n * 64 + (lane & 7) + ((lane >> 3) & 1) * 8;
    uint32_t b_koff = (lane >> 4) * 8;

    uint32_t sAh_u = smem_u32(sAh), sAl_u = smem_u32(sAl);
    uint32_t sBh_u = smem_u32(sBh), sBl_u = smem_u32(sBl);

    for (int kb = 0; kb < K; kb += BK) {
        // ---- fill 4 tiles: 128 rows x 32 cols bf16 each, uint4 (8 bf16) loads
        #pragma unroll
        for (int it = 0; it < 8; ++it) {
            int i = tid + it * 256;          // 0..2047
            int t = i >> 9, w = i & 511;
            int row = w >> 2, c8 = (w & 3) * 8;
            if (t < 2) {
                int r = m0 + row;
                uint4 val = make_uint4(0, 0, 0, 0);
                if (r < M)
                    val = *(const uint4*)((t == 0 ? Ah : Al) + (size_t)r * K + kb + c8);
                *(uint4*)((t == 0 ? sAh : sAl) + row * LDT + c8) = val;
            } else {
                const __nv_bfloat16* Bp = (t == 2) ? Bh : Bl;
                uint4 val = *(const uint4*)(Bp + (size_t)(n0 + row) * K + kb + c8);
                *(uint4*)((t == 2 ? sBh : sBl) + row * LDT + c8) = val;
            }
        }
        __syncthreads();

        #pragma unroll
        for (int ks = 0; ks < BK / 16; ++ks) {
            uint32_t aH[2][4], aL[2][4], bH[4][4], bL[4][4];
            #pragma unroll
            for (int mt = 0; mt < 2; ++mt) {
                uint32_t off = ((a_row + mt * 16) * LDT + ks * 16 + a_koff) * 2;
                ldsm4(aH[mt], sAh_u + off);
                ldsm4(aL[mt], sAl_u + off);
            }
            #pragma unroll
            for (int nb = 0; nb < 4; ++nb) {
                uint32_t off = ((b_nrow + nb * 16) * LDT + ks * 16 + b_koff) * 2;
                ldsm4(bH[nb], sBh_u + off);
                ldsm4(bL[nb], sBl_u + off);
            }
            #pragma unroll
            for (int mt = 0; mt < 2; ++mt) {
                #pragma unroll
                for (int j = 0; j < 8; ++j) {
                    int nb = j >> 1, par = j & 1;
                    // term0: Ah*Bh; term1: Ah*Bl; term2: Al*Bh
                    mma_bf16(acc[mt][j], aH[mt], bH[nb][par], bH[nb][par + 2]);
                    mma_bf16(acc[mt][j], aH[mt], bL[nb][par], bL[nb][par + 2]);
                    mma_bf16(acc[mt][j], aL[mt], bH[nb][par], bH[nb][par + 2]);
                }
            }
        }
        __syncthreads();
    }

    // ---- epilogue: add bias, store fp32
    #pragma unroll
    for (int mt = 0; mt < 2; ++mt) {
        int r0 = m0 + warp_m * 32 + mt * 16 + (lane >> 2);
        #pragma unroll
        for (int j = 0; j < 8; ++j) {
            int c = n0 + warp_n * 64 + j * 8 + (lane & 3) * 2;
            float2 bv = *(const float2*)(bias + c);
            if (r0 < M) {
                float2 o0 = make_float2(acc[mt][j][0] + bv.x, acc[mt][j][1] + bv.y);
                *(float2*)(C + (size_t)r0 * Ntot + c) = o0;
            }
            if (r0 + 8 < M) {
                float2 o1 = make_float2(acc[mt][j][2] + bv.x, acc[mt][j][3] + bv.y);
                *(float2*)(C + (size_t)(r0 + 8) * Ntot + c) = o1;
            }
        }
    }
}

// ---------------- attention layer 1: 4 heads, d=64, warp per (node,head) ----
__global__ void attn1_kernel(int n)
{
    int gw = (blockIdx.x * blockDim.x + threadIdx.x) >> 5;
    int lane = threadIdx.x & 31;
    int node = gw >> 2;
    int head = gw & 3;
    if (node >= n) return;

    int base = node * D1 + head * 64;
    float2 qv = *(const float2*)(g_q1 + base + 2 * lane);

    float m = -1e30f, l = 0.0f, a0 = 0.0f, a1 = 0.0f;
    int beg = g_offs[node], end = g_offs[node + 1];
    for (int p = beg; p < end; ++p) {
        int s = g_srcs[p];
        int sb = s * D1 + head * 64 + 2 * lane;
        float2 kv = *(const float2*)(g_k1 + sb);
        float d = qv.x * kv.x + qv.y * kv.y;
        #pragma unroll
        for (int o = 16; o; o >>= 1) d += __shfl_xor_sync(0xffffffffu, d, o);
        float logit = d * 0.125f;
        float mn = fmaxf(m, logit);
        float c  = __expf(m - mn);
        float pe = __expf(logit - mn);
        l = l * c + pe;
        float2 vv = *(const float2*)(g_v1 + sb);
        a0 = a0 * c + pe * vv.x;
        a1 = a1 * c + pe * vv.y;
        m = mn;
    }
    if (l > 0.0f) {
        float inv = 1.0f / l;
        g_h[base + 2 * lane]     += a0 * inv;
        g_h[base + 2 * lane + 1] += a1 * inv;
    }
}

// ---------------- attention layer 2: 1 head, d=128, warp per node -----------
__global__ void attn2_kernel(int n)
{
    int node = (blockIdx.x * blockDim.x + threadIdx.x) >> 5;
    int lane = threadIdx.x & 31;
    if (node >= n) return;

    int base = node * EMB + 4 * lane;
    float4 qv = *(const float4*)(g_q2 + base);

    float m = -1e30f, l = 0.0f;
    float a0 = 0.f, a1 = 0.f, a2 = 0.f, a3 = 0.f;
    int beg = g_offs[node], end = g_offs[node + 1];
    const float scale = 0.088388347648318447f;
    for (int p = beg; p < end; ++p) {
        int s = g_srcs[p];
        int sb = s * EMB + 4 * lane;
        float4 kv = *(const float4*)(g_k2 + sb);
        float d = qv.x * kv.x + qv.y * kv.y + qv.z * kv.z + qv.w * kv.w;
        #pragma unroll
        for (int o = 16; o; o >>= 1) d += __shfl_xor_sync(0xffffffffu, d, o);
        float logit = d * scale;
        float mn = fmaxf(m, logit);
        float c  = __expf(m - mn);
        float pe = __expf(logit - mn);
        l = l * c + pe;
        float4 vv = *(const float4*)(g_v2 + sb);
        a0 = a0 * c + pe * vv.x;
        a1 = a1 * c + pe * vv.y;
        a2 = a2 * c + pe * vv.z;
        a3 = a3 * c + pe * vv.w;
        m = mn;
    }
    if (l > 0.0f) {
        float inv = 1.0f / l;
        g_o2[base + 0] += a0 * inv;
        g_o2[base + 1] += a1 * inv;
        g_o2[base + 2] += a2 * inv;
        g_o2[base + 3] += a3 * inv;
    }
}

// ---------------- final mean over nodes (reads g_o2) -------------------------
__global__ void reduce_mean_kernel(float* __restrict__ out, int n) {
    int col = threadIdx.x;   // 128 threads
    float s = 0.0f;
    for (int r = blockIdx.x; r < n; r += gridDim.x)
        s += g_o2[(size_t)r * EMB + col];
    atomicAdd(&out[col], s * (1.0f / (float)n));
}

// ---------------- launch -----------------------------------------------------
extern "C" void kernel_launch(void* const* d_in, const int* in_sizes, int n_in,
                              void* d_out, int out_size)
{
    const float* x  = (const float*)d_in[0];
    const void*  ei = d_in[1];
    const float *Wq1 = (const float*)d_in[2],  *bq1 = (const float*)d_in[3];
    const float *Wk1 = (const float*)d_in[4],  *bk1 = (const float*)d_in[5];
    const float *Wv1 = (const float*)d_in[6],  *bv1 = (const float*)d_in[7];
    const float *Ws1 = (const float*)d_in[8],  *bs1 = (const float*)d_in[9];
    const float *Wq2 = (const float*)d_in[10], *bq2 = (const float*)d_in[11];
    const float *Wk2 = (const float*)d_in[12], *bk2 = (const float*)d_in[13];
    const float *Wv2 = (const float*)d_in[14], *bv2 = (const float*)d_in[15];
    const float *Ws2 = (const float*)d_in[16], *bs2 = (const float*)d_in[17];
    float* out = (float*)d_out;

    const int n = in_sizes[0] / INC;   // 50000
    const int e = in_sizes[1] / 2;     // 800000

    // ---- edge dtype detection + CSR build (by dst) ----
    {
        int threads = 256;
        detect_kernel<<<1, 32>>>(ei, n);
        init_kernel<<<(n + threads - 1) / threads, threads>>>(out, n);
        hist_kernel<<<(e + threads - 1) / threads, threads>>>(ei, e, n);
        int nchunks = (n + 511) / 512;
        scanA_kernel<<<nchunks, 512>>>(n);
        scanB_kernel<<<1, 32>>>(nchunks);
        scanC_kernel<<<(n + threads - 1) / threads, threads>>>(n);
        scatter_kernel<<<(e + threads - 1) / threads, threads>>>(ei, e, n);
    }

    // ---- input splits: x -> bf16 hi/lo, weights -> transposed bf16 hi/lo ----
    {
        int totx = n * INC;
        xsplit_kernel<<<(totx + 255) / 256, 256>>>(x, totx);
        wsplit_kernel<<<1024, 256>>>(Wq1, Wk1, Wv1, Ws1, Wq2, Wk2, Wv2, Ws2);
    }

    int mtiles = (n + 127) / 128;

    // ---- layer 1 projections (4 matrices, N=256 each -> 2 tiles/mat) ----
    {
        dim3 grid(8, mtiles);
        mma_gemm_kernel<<<grid, 256>>>(bq1, bk1, bv1, bs1, n, INC, 2, 0, 0, 0);
    }

    // ---- layer 1 attention (adds into g_h) + relu + split ----
    {
        int warps = n * 4;
        int blocks = (warps + 7) / 8;
        attn1_kernel<<<blocks, 256>>>(n);
        relu_split_kernel<<<1024, 256>>>(n * D1);
    }

    // ---- layer 2 projections (4 matrices, N=128 each -> 1 tile/mat) ----
    {
        dim3 grid(4, mtiles);
        mma_gemm_kernel<<<grid, 256>>>(bq2, bk2, bv2, bs2, n, D1, 1, 131072, 1, 4);
    }

    // ---- layer 2 attention (adds into g_o2) ----
    {
        int blocks = (n + 7) / 8;
        attn2_kernel<<<blocks, 256>>>(n);
    }

    // ---- final mean over nodes ----
    reduce_mean_kernel<<<256, EMB>>>(out, n);
}

// round 6
// speedup vs baseline: 2.1929x; 1.2194x over previous
#include <cuda_runtime.h>
#include <cuda_bf16.h>
#include <math.h>
#include <stdint.h>

// Problem constants (fixed by the dataset)
#define NN 50000
#define EE 800000
#define INC 128
#define D1 256     // HID*HEADS
#define EMB 128

// ---------------- scratch (device globals; no allocation allowed) ------------
__device__ float g_q1[NN * D1];
__device__ float g_k1[NN * D1];
__device__ float g_v1[NN * D1];
__device__ float g_h [NN * D1];   // skip + attention out (fp32)
__device__ float g_q2[NN * EMB];
__device__ float g_k2[NN * EMB];
__device__ float g_v2[NN * EMB];
__device__ float g_o2[NN * EMB];  // layer2 skip + attention out

// bf16 hi/lo splits for tensor-core GEMM inputs
__device__ __nv_bfloat16 g_xh[NN * INC];
__device__ __nv_bfloat16 g_xl[NN * INC];
__device__ __nv_bfloat16 g_hh[NN * D1];
__device__ __nv_bfloat16 g_hl[NN * D1];
// transposed+split weights: layer1 at [0, 131072) (4 mats * 256*128),
// layer2 at [131072, 262144) (4 mats * 128*256).  Layout: Wt[n][k] row-major.
__device__ __nv_bfloat16 g_wh[262144];
__device__ __nv_bfloat16 g_wl[262144];

__device__ int g_deg   [NN];
__device__ int g_cursor[NN];
__device__ int g_incl  [NN];
__device__ int g_offs  [NN + 1];
__device__ int g_part  [128];
__device__ int g_cbase [128];
__device__ int g_srcs  [EE];
__device__ int g_is64;            // 1 if edge_index is int64, 0 if int32

// selector -> scratch buffer (device-side only)
__device__ __forceinline__ float* buf_ptr(int sel) {
    switch (sel) {
        case 0: return g_q1;
        case 1: return g_k1;
        case 2: return g_v1;
        case 3: return g_h;
        case 4: return g_q2;
        case 5: return g_k2;
        case 6: return g_v2;
        default: return g_o2;
    }
}

// read edge_index[idx] under detected dtype
__device__ __forceinline__ int edge_val(const void* ei, long long idx) {
    if (g_is64) return (int)((const long long*)ei)[idx];
    return ((const int*)ei)[idx];
}

__device__ __forceinline__ uint32_t smem_u32(const void* p) {
    uint32_t a;
    asm("{ .reg .u64 t; cvta.to.shared.u64 t, %1; cvt.u32.u64 %0, t; }"
        : "=r"(a) : "l"(p));
    return a;
}

// ldmatrix x4 (b16, no transpose)
__device__ __forceinline__ void ldsm4(uint32_t* r, uint32_t addr) {
    asm volatile("ldmatrix.sync.aligned.m8n8.x4.shared.b16 {%0,%1,%2,%3}, [%4];"
                 : "=r"(r[0]), "=r"(r[1]), "=r"(r[2]), "=r"(r[3]) : "r"(addr));
}

// mma m16n8k16 bf16 -> fp32 accumulate
__device__ __forceinline__ void mma_bf16(float* d, const uint32_t* a,
                                         uint32_t b0, uint32_t b1) {
    asm volatile(
        "mma.sync.aligned.m16n8k16.row.col.f32.bf16.bf16.f32 "
        "{%0,%1,%2,%3}, {%4,%5,%6,%7}, {%8,%9}, {%0,%1,%2,%3};"
        : "+f"(d[0]), "+f"(d[1]), "+f"(d[2]), "+f"(d[3])
        : "r"(a[0]), "r"(a[1]), "r"(a[2]), "r"(a[3]), "r"(b0), "r"(b1));
}

// cp.async 16B with zero-fill when sz==0
__device__ __forceinline__ void cpasync16(uint32_t dst, const void* src, int sz) {
    asm volatile("cp.async.cg.shared.global [%0], [%1], 16, %2;"
                 :: "r"(dst), "l"(src), "r"(sz) : "memory");
}

// ---------------- dtype detection (reads only first 256 bytes) ---------------
__global__ void detect_kernel(const void* ei, int n) {
    if (threadIdx.x == 0 && blockIdx.x == 0) {
        const long long* p = (const long long*)ei;
        int ok = 1;
        for (int i = 0; i < 32; ++i) {
            long long v = p[i];
            if (v < 0 || v >= n) ok = 0;
        }
        g_is64 = ok;
    }
}

// ---------------- init: zero deg/cursor and output --------------------------
__global__ void init_kernel(float* out, int n) {
    int i = blockIdx.x * blockDim.x + threadIdx.x;
    if (i < n) { g_deg[i] = 0; g_cursor[i] = 0; }
    if (i < EMB) out[i] = 0.0f;
    if (i == 0) g_offs[0] = 0;
}

// ---------------- CSR build -------------------------------------------------
__global__ void hist_kernel(const void* __restrict__ ei, int e, int n) {
    int idx = blockIdx.x * blockDim.x + threadIdx.x;
    if (idx < e) {
        int d = edge_val(ei, (long long)e + idx);
        if (d >= 0 && d < n) atomicAdd(&g_deg[d], 1);
    }
}

__global__ void scanA_kernel(int n) {
    __shared__ int s[512];
    int t = threadIdx.x;
    int i = blockIdx.x * 512 + t;
    int v = (i < n) ? g_deg[i] : 0;
    s[t] = v;
    __syncthreads();
    #pragma unroll
    for (int off = 1; off < 512; off <<= 1) {
        int add = (t >= off) ? s[t - off] : 0;
        __syncthreads();
        s[t] += add;
        __syncthreads();
    }
    if (i < n) g_incl[i] = s[t];
    if (t == 511) g_part[blockIdx.x] = s[511];
}

__global__ void scanB_kernel(int nchunks) {
    if (threadIdx.x == 0 && blockIdx.x == 0) {
        int run = 0;
        for (int b = 0; b < nchunks; ++b) {
            int t = g_part[b];
            g_cbase[b] = run;
            run += t;
        }
    }
}

__global__ void scanC_kernel(int n) {
    int i = blockIdx.x * blockDim.x + threadIdx.x;
    if (i < n) g_offs[i + 1] = g_cbase[i >> 9] + g_incl[i];
}

__global__ void scatter_kernel(const void* __restrict__ ei, int e, int n) {
    int idx = blockIdx.x * blockDim.x + threadIdx.x;
    if (idx < e) {
        int d = edge_val(ei, (long long)e + idx);
        int s = edge_val(ei, idx);
        if (d >= 0 && d < n && s >= 0 && s < n) {
            int pos = g_offs[d] + atomicAdd(&g_cursor[d], 1);
            g_srcs[pos] = s;
        }
    }
}

// ---------------- bf16 split passes ------------------------------------------
__global__ void xsplit_kernel(const float* __restrict__ x, int total) {
    int i = blockIdx.x * blockDim.x + threadIdx.x;
    if (i < total) {
        float v = x[i];
        __nv_bfloat16 hi = __float2bfloat16(v);
        g_xh[i] = hi;
        g_xl[i] = __float2bfloat16(v - __bfloat162float(hi));
    }
}

// relu(g_h) -> (g_hh, g_hl)
__global__ void relu_split_kernel(int total) {
    int i = blockIdx.x * blockDim.x + threadIdx.x;
    int stride = gridDim.x * blockDim.x;
    for (; i < total; i += stride) {
        float v = fmaxf(g_h[i], 0.0f);
        __nv_bfloat16 hi = __float2bfloat16(v);
        g_hh[i] = hi;
        g_hl[i] = __float2bfloat16(v - __bfloat162float(hi));
    }
}

// transpose + split all 8 weight matrices into g_wh/g_wl
__global__ void wsplit_kernel(const float* w0, const float* w1, const float* w2, const float* w3,
                              const float* w4, const float* w5, const float* w6, const float* w7) {
    int tid = blockIdx.x * blockDim.x + threadIdx.x;
    if (tid >= 262144) return;
    float v;
    int idx;
    if (tid < 131072) {
        int m = tid >> 15, r = tid & 32767;
        int n = r >> 7, k = r & 127;
        const float* W = (m == 0) ? w0 : (m == 1) ? w1 : (m == 2) ? w2 : w3;
        v = W[k * 256 + n];
        idx = m * 32768 + n * 128 + k;
    } else {
        int e = tid - 131072;
        int m = e >> 15, r = e & 32767;
        int n = r >> 8, k = r & 255;
        const float* W = (m == 0) ? w4 : (m == 1) ? w5 : (m == 2) ? w6 : w7;
        v = W[k * 128 + n];
        idx = 131072 + m * 32768 + n * 256 + k;
    }
    __nv_bfloat16 hi = __float2bfloat16(v);
    g_wh[idx] = hi;
    g_wl[idx] = __float2bfloat16(v - __bfloat162float(hi));
}

// ---------------- mma.sync GEMM with 2-stage cp.async pipeline ----------------
// C[M,Ntot] 128x128 block tile; A[M,K] bf16 hi/lo, B = Wt[N][K] bf16 hi/lo.
// 3-term: Ah*Bh + Ah*Bl + Al*Bh, fp32 accum. 8 warps = 4(m) x 2(n).
#define BK 32
#define LDT 40                       // smem row stride in bf16 (80 B)
#define TILE_ELEMS (128 * LDT)       // 5120 elems = 10240 B
#define STAGE_ELEMS (4 * TILE_ELEMS) // 4 tiles (Ah, Al, Bh, Bl)
#define GEMM_SMEM_BYTES (2 * STAGE_ELEMS * 2)   // 81920 B

__global__ __launch_bounds__(256, 2)
void mma_gemm_kernel(const float* __restrict__ b0, const float* __restrict__ b1,
                     const float* __restrict__ b2, const float* __restrict__ b3,
                     int M, int K, int ntiles, int wt_base, int layer, int out_base)
{
    extern __shared__ __align__(16) __nv_bfloat16 sm[];

    int tid = threadIdx.x, wid = tid >> 5, lane = tid & 31;
    int mat = blockIdx.x / ntiles, nt0 = blockIdx.x % ntiles;
    int m0 = blockIdx.y * 128;
    int n0 = nt0 * 128;
    int Ntot = ntiles * 128;

    const __nv_bfloat16* Ah = layer ? g_hh : g_xh;
    const __nv_bfloat16* Al = layer ? g_hl : g_xl;
    const __nv_bfloat16* Bh = g_wh + wt_base + mat * 32768;
    const __nv_bfloat16* Bl = g_wl + wt_base + mat * 32768;
    float* C = buf_ptr(out_base + mat);
    const float* bias = (mat == 0) ? b0 : (mat == 1) ? b1 : (mat == 2) ? b2 : b3;

    int warp_m = wid >> 1;
    int warp_n = wid & 1;

    float acc[2][8][4];
    #pragma unroll
    for (int i = 0; i < 2; ++i)
        #pragma unroll
        for (int j = 0; j < 8; ++j)
            #pragma unroll
            for (int q = 0; q < 4; ++q) acc[i][j][q] = 0.0f;

    uint32_t smu = smem_u32(sm);

    // per-thread fixed load coords: 2048 chunks/stage, 8 per thread
    // chunk i: tile t=i>>9, w=i&511, row=w>>2, c8=(w&3)*8
    int nchunks = K / BK;

    // issue stage for chunk kc into buffer (kc&1)
    auto issue = [&](int kc) {
        int kb = kc * BK;
        uint32_t sbase = smu + (uint32_t)(kc & 1) * (STAGE_ELEMS * 2);
        #pragma unroll
        for (int it = 0; it < 8; ++it) {
            int i = tid + it * 256;
            int t = i >> 9, w = i & 511;
            int row = w >> 2, c8 = (w & 3) * 8;
            uint32_t dst = sbase + (uint32_t)(t * TILE_ELEMS + row * LDT + c8) * 2;
            if (t < 2) {
                int r = m0 + row;
                const __nv_bfloat16* src = (t == 0 ? Ah : Al);
                const void* sp = (r < M) ? (const void*)(src + (size_t)r * K + kb + c8)
                                         : (const void*)src;
                cpasync16(dst, sp, (r < M) ? 16 : 0);
            } else {
                const __nv_bfloat16* Bp = (t == 2) ? Bh : Bl;
                cpasync16(dst, Bp + (size_t)(n0 + row) * K + kb + c8, 16);
            }
        }
        asm volatile("cp.async.commit_group;" ::: "memory");
    };

    // ldmatrix source coords
    uint32_t a_row = warp_m * 32 + (lane & 15);
    uint32_t a_koff = (lane >> 4) * 8;
    uint32_t b_nrow = warp_n * 64 + (lane & 7) + ((lane >> 3) & 1) * 8;
    uint32_t b_koff = (lane >> 4) * 8;

    issue(0);

    for (int kc = 0; kc < nchunks; ++kc) {
        if (kc + 1 < nchunks) {
            issue(kc + 1);
            asm volatile("cp.async.wait_group 1;" ::: "memory");
        } else {
            asm volatile("cp.async.wait_group 0;" ::: "memory");
        }
        __syncthreads();

        uint32_t sbase = smu + (uint32_t)(kc & 1) * (STAGE_ELEMS * 2);
        uint32_t sAh_u = sbase;
        uint32_t sAl_u = sbase + TILE_ELEMS * 2;
        uint32_t sBh_u = sbase + 2 * TILE_ELEMS * 2;
        uint32_t sBl_u = sbase + 3 * TILE_ELEMS * 2;

        #pragma unroll
        for (int ks = 0; ks < BK / 16; ++ks) {
            uint32_t aH[2][4], aL[2][4], bH[4][4], bL[4][4];
            #pragma unroll
            for (int mt = 0; mt < 2; ++mt) {
                uint32_t off = ((a_row + mt * 16) * LDT + ks * 16 + a_koff) * 2;
                ldsm4(aH[mt], sAh_u + off);
                ldsm4(aL[mt], sAl_u + off);
            }
            #pragma unroll
            for (int nb = 0; nb < 4; ++nb) {
                uint32_t off = ((b_nrow + nb * 16) * LDT + ks * 16 + b_koff) * 2;
                ldsm4(bH[nb], sBh_u + off);
                ldsm4(bL[nb], sBl_u + off);
            }
            #pragma unroll
            for (int mt = 0; mt < 2; ++mt) {
                #pragma unroll
                for (int j = 0; j < 8; ++j) {
                    int nb = j >> 1, par = j & 1;
                    mma_bf16(acc[mt][j], aH[mt], bH[nb][par], bH[nb][par + 2]);
                    mma_bf16(acc[mt][j], aH[mt], bL[nb][par], bL[nb][par + 2]);
                    mma_bf16(acc[mt][j], aL[mt], bH[nb][par], bH[nb][par + 2]);
                }
            }
        }
        __syncthreads();
    }

    // ---- epilogue: add bias, store fp32
    #pragma unroll
    for (int mt = 0; mt < 2; ++mt) {
        int r0 = m0 + warp_m * 32 + mt * 16 + (lane >> 2);
        #pragma unroll
        for (int j = 0; j < 8; ++j) {
            int c = n0 + warp_n * 64 + j * 8 + (lane & 3) * 2;
            float2 bv = *(const float2*)(bias + c);
            if (r0 < M) {
                float2 o0 = make_float2(acc[mt][j][0] + bv.x, acc[mt][j][1] + bv.y);
                *(float2*)(C + (size_t)r0 * Ntot + c) = o0;
            }
            if (r0 + 8 < M) {
                float2 o1 = make_float2(acc[mt][j][2] + bv.x, acc[mt][j][3] + bv.y);
                *(float2*)(C + (size_t)(r0 + 8) * Ntot + c) = o1;
            }
        }
    }
}

// ---------------- attention layer 1: warp per node, 4 heads, 2-edge unroll ----
// lane group of 8 per head; each lane owns 8 floats of its head's d=64.
__global__ void attn1_kernel(int n)
{
    int node = (blockIdx.x * blockDim.x + threadIdx.x) >> 5;
    int lane = threadIdx.x & 31;
    if (node >= n) return;

    int off = (lane >> 3) * 64 + (lane & 7) * 8;
    const float* qb = g_q1 + (size_t)node * D1 + off;
    float4 q0 = *(const float4*)qb;
    float4 q1 = *(const float4*)(qb + 4);

    float m = -1e30f, l = 0.0f;
    float4 A0 = make_float4(0.f,0.f,0.f,0.f), A1 = make_float4(0.f,0.f,0.f,0.f);

    int beg = g_offs[node], end = g_offs[node + 1];
    int p = beg;
    for (; p + 2 <= end; p += 2) {
        int s0 = g_srcs[p], s1 = g_srcs[p + 1];
        const float* k0b = g_k1 + (size_t)s0 * D1 + off;
        const float* k1b = g_k1 + (size_t)s1 * D1 + off;
        const float* v0b = g_v1 + (size_t)s0 * D1 + off;
        const float* v1b = g_v1 + (size_t)s1 * D1 + off;
        float4 ka = *(const float4*)k0b, kb = *(const float4*)(k0b + 4);
        float4 kc = *(const float4*)k1b, kd = *(const float4*)(k1b + 4);
        float4 va = *(const float4*)v0b, vb = *(const float4*)(v0b + 4);
        float4 vc = *(const float4*)v1b, vd = *(const float4*)(v1b + 4);

        float d0 = q0.x*ka.x + q0.y*ka.y + q0.z*ka.z + q0.w*ka.w
                 + q1.x*kb.x + q1.y*kb.y + q1.z*kb.z + q1.w*kb.w;
        float d1 = q0.x*kc.x + q0.y*kc.y + q0.z*kc.z + q0.w*kc.w
                 + q1.x*kd.x + q1.y*kd.y + q1.z*kd.z + q1.w*kd.w;
        #pragma unroll
        for (int o = 4; o; o >>= 1) {
            d0 += __shfl_xor_sync(0xffffffffu, d0, o);
            d1 += __shfl_xor_sync(0xffffffffu, d1, o);
        }
        {
            float logit = d0 * 0.125f;
            float mn = fmaxf(m, logit);
            float c = __expf(m - mn), pe = __expf(logit - mn);
            l = l * c + pe;
            A0.x = A0.x*c + pe*va.x; A0.y = A0.y*c + pe*va.y;
            A0.z = A0.z*c + pe*va.z; A0.w = A0.w*c + pe*va.w;
            A1.x = A1.x*c + pe*vb.x; A1.y = A1.y*c + pe*vb.y;
            A1.z = A1.z*c + pe*vb.z; A1.w = A1.w*c + pe*vb.w;
            m = mn;
        }
        {
            float logit = d1 * 0.125f;
            float mn = fmaxf(m, logit);
            float c = __expf(m - mn), pe = __expf(logit - mn);
            l = l * c + pe;
            A0.x = A0.x*c + pe*vc.x; A0.y = A0.y*c + pe*vc.y;
            A0.z = A0.z*c + pe*vc.z; A0.w = A0.w*c + pe*vc.w;
            A1.x = A1.x*c + pe*vd.x; A1.y = A1.y*c + pe*vd.y;
            A1.z = A1.z*c + pe*vd.z; A1.w = A1.w*c + pe*vd.w;
            m = mn;
        }
    }
    if (p < end) {
        int s0 = g_srcs[p];
        const float* k0b = g_k1 + (size_t)s0 * D1 + off;
        const float* v0b = g_v1 + (size_t)s0 * D1 + off;
        float4 ka = *(const float4*)k0b, kb = *(const float4*)(k0b + 4);
        float4 va = *(const float4*)v0b, vb = *(const float4*)(v0b + 4);
        float d0 = q0.x*ka.x + q0.y*ka.y + q0.z*ka.z + q0.w*ka.w
                 + q1.x*kb.x + q1.y*kb.y + q1.z*kb.z + q1.w*kb.w;
        #pragma unroll
        for (int o = 4; o; o >>= 1) d0 += __shfl_xor_sync(0xffffffffu, d0, o);
        float logit = d0 * 0.125f;
        float mn = fmaxf(m, logit);
        float c = __expf(m - mn), pe = __expf(logit - mn);
        l = l * c + pe;
        A0.x = A0.x*c + pe*va.x; A0.y = A0.y*c + pe*va.y;
        A0.z = A0.z*c + pe*va.z; A0.w = A0.w*c + pe*va.w;
        A1.x = A1.x*c + pe*vb.x; A1.y = A1.y*c + pe*vb.y;
        A1.z = A1.z*c + pe*vb.z; A1.w = A1.w*c + pe*vb.w;
        m = mn;
    }
    if (l > 0.0f) {
        float inv = 1.0f / l;
        float* hb = g_h + (size_t)node * D1 + off;
        float4 h0 = *(float4*)hb;
        float4 h1 = *(float4*)(hb + 4);
        h0.x += A0.x*inv; h0.y += A0.y*inv; h0.z += A0.z*inv; h0.w += A0.w*inv;
        h1.x += A1.x*inv; h1.y += A1.y*inv; h1.z += A1.z*inv; h1.w += A1.w*inv;
        *(float4*)hb = h0;
        *(float4*)(hb + 4) = h1;
    }
}

// ---------------- attention layer 2: 1 head, d=128, warp per node, unroll 2 --
__global__ void attn2_kernel(int n)
{
    int node = (blockIdx.x * blockDim.x + threadIdx.x) >> 5;
    int lane = threadIdx.x & 31;
    if (node >= n) return;

    int base = node * EMB + 4 * lane;
    float4 qv = *(const float4*)(g_q2 + base);

    float m = -1e30f, l = 0.0f;
    float4 A = make_float4(0.f,0.f,0.f,0.f);
    int beg = g_offs[node], end = g_offs[node + 1];
    const float scale = 0.088388347648318447f;   // 1/sqrt(128)

    int p = beg;
    for (; p + 2 <= end; p += 2) {
        int s0 = g_srcs[p], s1 = g_srcs[p + 1];
        float4 k0 = *(const float4*)(g_k2 + (size_t)s0 * EMB + 4 * lane);
        float4 k1 = *(const float4*)(g_k2 + (size_t)s1 * EMB + 4 * lane);
        float4 v0 = *(const float4*)(g_v2 + (size_t)s0 * EMB + 4 * lane);
        float4 v1 = *(const float4*)(g_v2 + (size_t)s1 * EMB + 4 * lane);
        float d0 = qv.x*k0.x + qv.y*k0.y + qv.z*k0.z + qv.w*k0.w;
        float d1 = qv.x*k1.x + qv.y*k1.y + qv.z*k1.z + qv.w*k1.w;
        #pragma unroll
        for (int o = 16; o; o >>= 1) {
            d0 += __shfl_xor_sync(0xffffffffu, d0, o);
            d1 += __shfl_xor_sync(0xffffffffu, d1, o);
        }
        {
            float logit = d0 * scale;
            float mn = fmaxf(m, logit);
            float c = __expf(m - mn), pe = __expf(logit - mn);
            l = l * c + pe;
            A.x = A.x*c + pe*v0.x; A.y = A.y*c + pe*v0.y;
            A.z = A.z*c + pe*v0.z; A.w = A.w*c + pe*v0.w;
            m = mn;
        }
        {
            float logit = d1 * scale;
            float mn = fmaxf(m, logit);
            float c = __expf(m - mn), pe = __expf(logit - mn);
            l = l * c + pe;
            A.x = A.x*c + pe*v1.x; A.y = A.y*c + pe*v1.y;
            A.z = A.z*c + pe*v1.z; A.w = A.w*c + pe*v1.w;
            m = mn;
        }
    }
    if (p < end) {
        int s0 = g_srcs[p];
        float4 k0 = *(const float4*)(g_k2 + (size_t)s0 * EMB + 4 * lane);
        float4 v0 = *(const float4*)(g_v2 + (size_t)s0 * EMB + 4 * lane);
        float d0 = qv.x*k0.x + qv.y*k0.y + qv.z*k0.z + qv.w*k0.w;
        #pragma unroll
        for (int o = 16; o; o >>= 1) d0 += __shfl_xor_sync(0xffffffffu, d0, o);
        float logit = d0 * scale;
        float mn = fmaxf(m, logit);
        float c = __expf(m - mn), pe = __expf(logit - mn);
        l = l * c + pe;
        A.x = A.x*c + pe*v0.x; A.y = A.y*c + pe*v0.y;
        A.z = A.z*c + pe*v0.z; A.w = A.w*c + pe*v0.w;
        m = mn;
    }
    if (l > 0.0f) {
        float inv = 1.0f / l;
        float4 o = *(float4*)(g_o2 + base);
        o.x += A.x*inv; o.y += A.y*inv; o.z += A.z*inv; o.w += A.w*inv;
        *(float4*)(g_o2 + base) = o;
    }
}

// ---------------- final mean over nodes (reads g_o2) -------------------------
__global__ void reduce_mean_kernel(float* __restrict__ out, int n) {
    int col = threadIdx.x;   // 128 threads
    float s = 0.0f;
    for (int r = blockIdx.x; r < n; r += gridDim.x)
        s += g_o2[(size_t)r * EMB + col];
    atomicAdd(&out[col], s * (1.0f / (float)n));
}

// ---------------- launch -----------------------------------------------------
extern "C" void kernel_launch(void* const* d_in, const int* in_sizes, int n_in,
                              void* d_out, int out_size)
{
    const float* x  = (const float*)d_in[0];
    const void*  ei = d_in[1];
    const float *Wq1 = (const float*)d_in[2],  *bq1 = (const float*)d_in[3];
    const float *Wk1 = (const float*)d_in[4],  *bk1 = (const float*)d_in[5];
    const float *Wv1 = (const float*)d_in[6],  *bv1 = (const float*)d_in[7];
    const float *Ws1 = (const float*)d_in[8],  *bs1 = (const float*)d_in[9];
    const float *Wq2 = (const float*)d_in[10], *bq2 = (const float*)d_in[11];
    const float *Wk2 = (const float*)d_in[12], *bk2 = (const float*)d_in[13];
    const float *Wv2 = (const float*)d_in[14], *bv2 = (const float*)d_in[15];
    const float *Ws2 = (const float*)d_in[16], *bs2 = (const float*)d_in[17];
    float* out = (float*)d_out;

    const int n = in_sizes[0] / INC;   // 50000
    const int e = in_sizes[1] / 2;     // 800000

    cudaFuncSetAttribute(mma_gemm_kernel,
                         cudaFuncAttributeMaxDynamicSharedMemorySize, GEMM_SMEM_BYTES);

    // ---- edge dtype detection + CSR build (by dst) ----
    {
        int threads = 256;
        detect_kernel<<<1, 32>>>(ei, n);
        init_kernel<<<(n + threads - 1) / threads, threads>>>(out, n);
        hist_kernel<<<(e + threads - 1) / threads, threads>>>(ei, e, n);
        int nchunks = (n + 511) / 512;
        scanA_kernel<<<nchunks, 512>>>(n);
        scanB_kernel<<<1, 32>>>(nchunks);
        scanC_kernel<<<(n + threads - 1) / threads, threads>>>(n);
        scatter_kernel<<<(e + threads - 1) / threads, threads>>>(ei, e, n);
    }

    // ---- input splits: x -> bf16 hi/lo, weights -> transposed bf16 hi/lo ----
    {
        int totx = n * INC;
        xsplit_kernel<<<(totx + 255) / 256, 256>>>(x, totx);
        wsplit_kernel<<<1024, 256>>>(Wq1, Wk1, Wv1, Ws1, Wq2, Wk2, Wv2, Ws2);
    }

    int mtiles = (n + 127) / 128;

    // ---- layer 1 projections (4 matrices, N=256 each -> 2 tiles/mat) ----
    {
        dim3 grid(8, mtiles);
        mma_gemm_kernel<<<grid, 256, GEMM_SMEM_BYTES>>>(bq1, bk1, bv1, bs1,
                                                        n, INC, 2, 0, 0, 0);
    }

    // ---- layer 1 attention (adds into g_h) + relu + split ----
    {
        int blocks = (n + 7) / 8;
        attn1_kernel<<<blocks, 256>>>(n);
        relu_split_kernel<<<1024, 256>>>(n * D1);
    }

    // ---- layer 2 projections (4 matrices, N=128 each -> 1 tile/mat) ----
    {
        dim3 grid(4, mtiles);
        mma_gemm_kernel<<<grid, 256, GEMM_SMEM_BYTES>>>(bq2, bk2, bv2, bs2,
                                                        n, D1, 1, 131072, 1, 4);
    }

    // ---- layer 2 attention (adds into g_o2) ----
    {
        int blocks = (n + 7) / 8;
        attn2_kernel<<<blocks, 256>>>(n);
    }

    // ---- final mean over nodes ----
    reduce_mean_kernel<<<256, EMB>>>(out, n);
}

// round 7
// speedup vs baseline: 2.2288x; 1.0164x over previous
#include <cuda_runtime.h>
#include <cuda_bf16.h>
#include <math.h>
#include <stdint.h>

// Problem constants (fixed by the dataset)
#define NN 50000
#define EE 800000
#define INC 128
#define D1 256     // HID*HEADS
#define EMB 128

// ---------------- scratch (device globals; no allocation allowed) ------------
__device__ float g_q1[NN * D1];
__device__ float g_k1[NN * D1];
__device__ float g_v1[NN * D1];
__device__ float g_h [NN * D1];   // layer1 skip (from GEMM)
__device__ float g_q2[NN * EMB];
__device__ float g_k2[NN * EMB];
__device__ float g_v2[NN * EMB];
__device__ float g_o2[NN * EMB];  // layer2 skip + attention out

// bf16 hi/lo splits for tensor-core GEMM inputs
__device__ __nv_bfloat16 g_xh[NN * INC];
__device__ __nv_bfloat16 g_xl[NN * INC];
__device__ __nv_bfloat16 g_hh[NN * D1];
__device__ __nv_bfloat16 g_hl[NN * D1];
// transposed+split weights: layer1 at [0, 131072), layer2 at [131072, 262144).
__device__ __nv_bfloat16 g_wh[262144];
__device__ __nv_bfloat16 g_wl[262144];

__device__ int g_deg   [NN];
__device__ int g_cursor[NN];
__device__ int g_incl  [NN];
__device__ int g_offs  [NN + 1];
__device__ int g_part  [128];
__device__ int g_cbase [128];
__device__ int g_srcs  [EE];
__device__ int g_is64;            // 1 if edge_index is int64, 0 if int32

// selector -> scratch buffer (device-side only)
__device__ __forceinline__ float* buf_ptr(int sel) {
    switch (sel) {
        case 0: return g_q1;
        case 1: return g_k1;
        case 2: return g_v1;
        case 3: return g_h;
        case 4: return g_q2;
        case 5: return g_k2;
        case 6: return g_v2;
        default: return g_o2;
    }
}

__device__ __forceinline__ int edge_val(const void* ei, long long idx) {
    if (g_is64) return (int)((const long long*)ei)[idx];
    return ((const int*)ei)[idx];
}

__device__ __forceinline__ uint32_t smem_u32(const void* p) {
    uint32_t a;
    asm("{ .reg .u64 t; cvta.to.shared.u64 t, %1; cvt.u32.u64 %0, t; }"
        : "=r"(a) : "l"(p));
    return a;
}

__device__ __forceinline__ void ldsm4(uint32_t* r, uint32_t addr) {
    asm volatile("ldmatrix.sync.aligned.m8n8.x4.shared.b16 {%0,%1,%2,%3}, [%4];"
                 : "=r"(r[0]), "=r"(r[1]), "=r"(r[2]), "=r"(r[3]) : "r"(addr));
}

__device__ __forceinline__ void mma_bf16(float* d, const uint32_t* a,
                                         uint32_t b0, uint32_t b1) {
    asm volatile(
        "mma.sync.aligned.m16n8k16.row.col.f32.bf16.bf16.f32 "
        "{%0,%1,%2,%3}, {%4,%5,%6,%7}, {%8,%9}, {%0,%1,%2,%3};"
        : "+f"(d[0]), "+f"(d[1]), "+f"(d[2]), "+f"(d[3])
        : "r"(a[0]), "r"(a[1]), "r"(a[2]), "r"(a[3]), "r"(b0), "r"(b1));
}

__device__ __forceinline__ void cpasync16(uint32_t dst, const void* src, int sz) {
    asm volatile("cp.async.cg.shared.global [%0], [%1], 16, %2;"
                 :: "r"(dst), "l"(src), "r"(sz) : "memory");
}

// ---------------- init (+ edge dtype detection) ------------------------------
__global__ void init_kernel(const void* ei, float* out, int n) {
    int i = blockIdx.x * blockDim.x + threadIdx.x;
    if (i < n) { g_deg[i] = 0; g_cursor[i] = 0; }
    if (i < EMB) out[i] = 0.0f;
    if (i == 0) {
        g_offs[0] = 0;
        const long long* p = (const long long*)ei;
        int ok = 1;
        for (int j = 0; j < 32; ++j) {
            long long v = p[j];
            if (v < 0 || v >= n) ok = 0;
        }
        g_is64 = ok;
    }
}

// ---------------- CSR build -------------------------------------------------
__global__ void hist_kernel(const void* __restrict__ ei, int e, int n) {
    int idx = blockIdx.x * blockDim.x + threadIdx.x;
    if (idx < e) {
        int d = edge_val(ei, (long long)e + idx);
        if (d >= 0 && d < n) atomicAdd(&g_deg[d], 1);
    }
}

__global__ void scanA_kernel(int n) {
    __shared__ int s[512];
    int t = threadIdx.x;
    int i = blockIdx.x * 512 + t;
    int v = (i < n) ? g_deg[i] : 0;
    s[t] = v;
    __syncthreads();
    #pragma unroll
    for (int off = 1; off < 512; off <<= 1) {
        int add = (t >= off) ? s[t - off] : 0;
        __syncthreads();
        s[t] += add;
        __syncthreads();
    }
    if (i < n) g_incl[i] = s[t];
    if (t == 511) g_part[blockIdx.x] = s[511];
}

__global__ void scanB_kernel(int nchunks) {
    if (threadIdx.x == 0 && blockIdx.x == 0) {
        int run = 0;
        for (int b = 0; b < nchunks; ++b) {
            int t = g_part[b];
            g_cbase[b] = run;
            run += t;
        }
    }
}

__global__ void scanC_kernel(int n) {
    int i = blockIdx.x * blockDim.x + threadIdx.x;
    if (i < n) g_offs[i + 1] = g_cbase[i >> 9] + g_incl[i];
}

__global__ void scatter_kernel(const void* __restrict__ ei, int e, int n) {
    int idx = blockIdx.x * blockDim.x + threadIdx.x;
    if (idx < e) {
        int d = edge_val(ei, (long long)e + idx);
        int s = edge_val(ei, idx);
        if (d >= 0 && d < n && s >= 0 && s < n) {
            int pos = g_offs[d] + atomicAdd(&g_cursor[d], 1);
            g_srcs[pos] = s;
        }
    }
}

// ---------------- bf16 split passes ------------------------------------------
__global__ void xsplit_kernel(const float* __restrict__ x, int total) {
    int i = blockIdx.x * blockDim.x + threadIdx.x;
    if (i < total) {
        float v = x[i];
        __nv_bfloat16 hi = __float2bfloat16(v);
        g_xh[i] = hi;
        g_xl[i] = __float2bfloat16(v - __bfloat162float(hi));
    }
}

__global__ void wsplit_kernel(const float* w0, const float* w1, const float* w2, const float* w3,
                              const float* w4, const float* w5, const float* w6, const float* w7) {
    int tid = blockIdx.x * blockDim.x + threadIdx.x;
    if (tid >= 262144) return;
    float v;
    int idx;
    if (tid < 131072) {
        int m = tid >> 15, r = tid & 32767;
        int n = r >> 7, k = r & 127;
        const float* W = (m == 0) ? w0 : (m == 1) ? w1 : (m == 2) ? w2 : w3;
        v = W[k * 256 + n];
        idx = m * 32768 + n * 128 + k;
    } else {
        int e = tid - 131072;
        int m = e >> 15, r = e & 32767;
        int n = r >> 8, k = r & 255;
        const float* W = (m == 0) ? w4 : (m == 1) ? w5 : (m == 2) ? w6 : w7;
        v = W[k * 128 + n];
        idx = 131072 + m * 32768 + n * 256 + k;
    }
    __nv_bfloat16 hi = __float2bfloat16(v);
    g_wh[idx] = hi;
    g_wl[idx] = __float2bfloat16(v - __bfloat162float(hi));
}

// ---------------- mma.sync GEMM with 2-stage cp.async pipeline ----------------
#define BK 32
#define LDT 40
#define TILE_ELEMS (128 * LDT)
#define STAGE_ELEMS (4 * TILE_ELEMS)
#define GEMM_SMEM_BYTES (2 * STAGE_ELEMS * 2)

__global__ __launch_bounds__(256, 2)
void mma_gemm_kernel(const float* __restrict__ b0, const float* __restrict__ b1,
                     const float* __restrict__ b2, const float* __restrict__ b3,
                     int M, int K, int ntiles, int wt_base, int layer, int out_base)
{
    extern __shared__ __align__(16) __nv_bfloat16 sm[];

    int tid = threadIdx.x, wid = tid >> 5, lane = tid & 31;
    int mat = blockIdx.x / ntiles, nt0 = blockIdx.x % ntiles;
    int m0 = blockIdx.y * 128;
    int n0 = nt0 * 128;
    int Ntot = ntiles * 128;

    const __nv_bfloat16* Ah = layer ? g_hh : g_xh;
    const __nv_bfloat16* Al = layer ? g_hl : g_xl;
    const __nv_bfloat16* Bh = g_wh + wt_base + mat * 32768;
    const __nv_bfloat16* Bl = g_wl + wt_base + mat * 32768;
    float* C = buf_ptr(out_base + mat);
    const float* bias = (mat == 0) ? b0 : (mat == 1) ? b1 : (mat == 2) ? b2 : b3;

    int warp_m = wid >> 1;
    int warp_n = wid & 1;

    float acc[2][8][4];
    #pragma unroll
    for (int i = 0; i < 2; ++i)
        #pragma unroll
        for (int j = 0; j < 8; ++j)
            #pragma unroll
            for (int q = 0; q < 4; ++q) acc[i][j][q] = 0.0f;

    uint32_t smu = smem_u32(sm);
    int nchunks = K / BK;

    auto issue = [&](int kc) {
        int kb = kc * BK;
        uint32_t sbase = smu + (uint32_t)(kc & 1) * (STAGE_ELEMS * 2);
        #pragma unroll
        for (int it = 0; it < 8; ++it) {
            int i = tid + it * 256;
            int t = i >> 9, w = i & 511;
            int row = w >> 2, c8 = (w & 3) * 8;
            uint32_t dst = sbase + (uint32_t)(t * TILE_ELEMS + row * LDT + c8) * 2;
            if (t < 2) {
                int r = m0 + row;
                const __nv_bfloat16* src = (t == 0 ? Ah : Al);
                const void* sp = (r < M) ? (const void*)(src + (size_t)r * K + kb + c8)
                                         : (const void*)src;
                cpasync16(dst, sp, (r < M) ? 16 : 0);
            } else {
                const __nv_bfloat16* Bp = (t == 2) ? Bh : Bl;
                cpasync16(dst, Bp + (size_t)(n0 + row) * K + kb + c8, 16);
            }
        }
        asm volatile("cp.async.commit_group;" ::: "memory");
    };

    uint32_t a_row = warp_m * 32 + (lane & 15);
    uint32_t a_koff = (lane >> 4) * 8;
    uint32_t b_nrow = warp_n * 64 + (lane & 7) + ((lane >> 3) & 1) * 8;
    uint32_t b_koff = (lane >> 4) * 8;

    issue(0);

    for (int kc = 0; kc < nchunks; ++kc) {
        if (kc + 1 < nchunks) {
            issue(kc + 1);
            asm volatile("cp.async.wait_group 1;" ::: "memory");
        } else {
            asm volatile("cp.async.wait_group 0;" ::: "memory");
        }
        __syncthreads();

        uint32_t sbase = smu + (uint32_t)(kc & 1) * (STAGE_ELEMS * 2);
        uint32_t sAh_u = sbase;
        uint32_t sAl_u = sbase + TILE_ELEMS * 2;
        uint32_t sBh_u = sbase + 2 * TILE_ELEMS * 2;
        uint32_t sBl_u = sbase + 3 * TILE_ELEMS * 2;

        #pragma unroll
        for (int ks = 0; ks < BK / 16; ++ks) {
            uint32_t aH[2][4], aL[2][4], bH[4][4], bL[4][4];
            #pragma unroll
            for (int mt = 0; mt < 2; ++mt) {
                uint32_t off = ((a_row + mt * 16) * LDT + ks * 16 + a_koff) * 2;
                ldsm4(aH[mt], sAh_u + off);
                ldsm4(aL[mt], sAl_u + off);
            }
            #pragma unroll
            for (int nb = 0; nb < 4; ++nb) {
                uint32_t off = ((b_nrow + nb * 16) * LDT + ks * 16 + b_koff) * 2;
                ldsm4(bH[nb], sBh_u + off);
                ldsm4(bL[nb], sBl_u + off);
            }
            #pragma unroll
            for (int mt = 0; mt < 2; ++mt) {
                #pragma unroll
                for (int j = 0; j < 8; ++j) {
                    int nb = j >> 1, par = j & 1;
                    mma_bf16(acc[mt][j], aH[mt], bH[nb][par], bH[nb][par + 2]);
                    mma_bf16(acc[mt][j], aH[mt], bL[nb][par], bL[nb][par + 2]);
                    mma_bf16(acc[mt][j], aL[mt], bH[nb][par], bH[nb][par + 2]);
                }
            }
        }
        __syncthreads();
    }

    #pragma unroll
    for (int mt = 0; mt < 2; ++mt) {
        int r0 = m0 + warp_m * 32 + mt * 16 + (lane >> 2);
        #pragma unroll
        for (int j = 0; j < 8; ++j) {
            int c = n0 + warp_n * 64 + j * 8 + (lane & 3) * 2;
            float2 bv = *(const float2*)(bias + c);
            if (r0 < M) {
                float2 o0 = make_float2(acc[mt][j][0] + bv.x, acc[mt][j][1] + bv.y);
                *(float2*)(C + (size_t)r0 * Ntot + c) = o0;
            }
            if (r0 + 8 < M) {
                float2 o1 = make_float2(acc[mt][j][2] + bv.x, acc[mt][j][3] + bv.y);
                *(float2*)(C + (size_t)(r0 + 8) * Ntot + c) = o1;
            }
        }
    }
}

// ---------------- attention layer 1 (fused skip+attn+relu+split) -------------
// warp per node, 4 heads via lane groups of 8; each lane owns 8 floats.
// unroll 4 for gather MLP. Writes g_hh/g_hl directly (no fp32 h output).
__global__ void attn1_kernel(int n)
{
    int node = (blockIdx.x * blockDim.x + threadIdx.x) >> 5;
    int lane = threadIdx.x & 31;
    if (node >= n) return;

    int off = (lane >> 3) * 64 + (lane & 7) * 8;
    const float* qb = g_q1 + (size_t)node * D1 + off;
    float4 q0 = *(const float4*)qb;
    float4 q1 = *(const float4*)(qb + 4);

    float m = -1e30f, l = 0.0f;
    float4 A0 = make_float4(0.f,0.f,0.f,0.f), A1 = make_float4(0.f,0.f,0.f,0.f);

    int beg = g_offs[node], end = g_offs[node + 1];
    int p = beg;
    for (; p + 4 <= end; p += 4) {
        float4 K0[4], K1[4], V0[4], V1[4];
        #pragma unroll
        for (int j = 0; j < 4; ++j) {
            int s = g_srcs[p + j];
            const float* kb = g_k1 + (size_t)s * D1 + off;
            const float* vb = g_v1 + (size_t)s * D1 + off;
            K0[j] = *(const float4*)kb;  K1[j] = *(const float4*)(kb + 4);
            V0[j] = *(const float4*)vb;  V1[j] = *(const float4*)(vb + 4);
        }
        float d[4];
        #pragma unroll
        for (int j = 0; j < 4; ++j)
            d[j] = q0.x*K0[j].x + q0.y*K0[j].y + q0.z*K0[j].z + q0.w*K0[j].w
                 + q1.x*K1[j].x + q1.y*K1[j].y + q1.z*K1[j].z + q1.w*K1[j].w;
        #pragma unroll
        for (int o = 4; o; o >>= 1)
            #pragma unroll
            for (int j = 0; j < 4; ++j)
                d[j] += __shfl_xor_sync(0xffffffffu, d[j], o);
        #pragma unroll
        for (int j = 0; j < 4; ++j) {
            float logit = d[j] * 0.125f;
            float mn = fmaxf(m, logit);
            float c = __expf(m - mn), pe = __expf(logit - mn);
            l = l * c + pe;
            A0.x = A0.x*c + pe*V0[j].x; A0.y = A0.y*c + pe*V0[j].y;
            A0.z = A0.z*c + pe*V0[j].z; A0.w = A0.w*c + pe*V0[j].w;
            A1.x = A1.x*c + pe*V1[j].x; A1.y = A1.y*c + pe*V1[j].y;
            A1.z = A1.z*c + pe*V1[j].z; A1.w = A1.w*c + pe*V1[j].w;
            m = mn;
        }
    }
    for (; p < end; ++p) {
        int s = g_srcs[p];
        const float* kb = g_k1 + (size_t)s * D1 + off;
        const float* vb = g_v1 + (size_t)s * D1 + off;
        float4 ka = *(const float4*)kb, kc4 = *(const float4*)(kb + 4);
        float4 va = *(const float4*)vb, vb4 = *(const float4*)(vb + 4);
        float d0 = q0.x*ka.x + q0.y*ka.y + q0.z*ka.z + q0.w*ka.w
                 + q1.x*kc4.x + q1.y*kc4.y + q1.z*kc4.z + q1.w*kc4.w;
        #pragma unroll
        for (int o = 4; o; o >>= 1) d0 += __shfl_xor_sync(0xffffffffu, d0, o);
        float logit = d0 * 0.125f;
        float mn = fmaxf(m, logit);
        float c = __expf(m - mn), pe = __expf(logit - mn);
        l = l * c + pe;
        A0.x = A0.x*c + pe*va.x; A0.y = A0.y*c + pe*va.y;
        A0.z = A0.z*c + pe*va.z; A0.w = A0.w*c + pe*va.w;
        A1.x = A1.x*c + pe*vb4.x; A1.y = A1.y*c + pe*vb4.y;
        A1.z = A1.z*c + pe*vb4.z; A1.w = A1.w*c + pe*vb4.w;
        m = mn;
    }

    float inv = (l > 0.0f) ? 1.0f / l : 0.0f;
    const float* hb = g_h + (size_t)node * D1 + off;
    float4 h0 = *(const float4*)hb;
    float4 h1 = *(const float4*)(hb + 4);
    float vals[8];
    vals[0] = fmaxf(h0.x + A0.x*inv, 0.0f);
    vals[1] = fmaxf(h0.y + A0.y*inv, 0.0f);
    vals[2] = fmaxf(h0.z + A0.z*inv, 0.0f);
    vals[3] = fmaxf(h0.w + A0.w*inv, 0.0f);
    vals[4] = fmaxf(h1.x + A1.x*inv, 0.0f);
    vals[5] = fmaxf(h1.y + A1.y*inv, 0.0f);
    vals[6] = fmaxf(h1.z + A1.z*inv, 0.0f);
    vals[7] = fmaxf(h1.w + A1.w*inv, 0.0f);

    union { uint4 u; __nv_bfloat16 b[8]; } hi_u, lo_u;
    #pragma unroll
    for (int j = 0; j < 8; ++j) {
        __nv_bfloat16 hi = __float2bfloat16(vals[j]);
        hi_u.b[j] = hi;
        lo_u.b[j] = __float2bfloat16(vals[j] - __bfloat162float(hi));
    }
    *(uint4*)(g_hh + (size_t)node * D1 + off) = hi_u.u;
    *(uint4*)(g_hl + (size_t)node * D1 + off) = lo_u.u;
}

// ---------------- attention layer 2: 1 head, d=128, warp per node, unroll 4 --
__global__ void attn2_kernel(int n)
{
    int node = (blockIdx.x * blockDim.x + threadIdx.x) >> 5;
    int lane = threadIdx.x & 31;
    if (node >= n) return;

    int base = node * EMB + 4 * lane;
    float4 qv = *(const float4*)(g_q2 + base);

    float m = -1e30f, l = 0.0f;
    float4 A = make_float4(0.f,0.f,0.f,0.f);
    int beg = g_offs[node], end = g_offs[node + 1];
    const float scale = 0.088388347648318447f;   // 1/sqrt(128)

    int p = beg;
    for (; p + 4 <= end; p += 4) {
        float4 K[4], V[4];
        #pragma unroll
        for (int j = 0; j < 4; ++j) {
            int s = g_srcs[p + j];
            K[j] = *(const float4*)(g_k2 + (size_t)s * EMB + 4 * lane);
            V[j] = *(const float4*)(g_v2 + (size_t)s * EMB + 4 * lane);
        }
        float d[4];
        #pragma unroll
        for (int j = 0; j < 4; ++j)
            d[j] = qv.x*K[j].x + qv.y*K[j].y + qv.z*K[j].z + qv.w*K[j].w;
        #pragma unroll
        for (int o = 16; o; o >>= 1)
            #pragma unroll
            for (int j = 0; j < 4; ++j)
                d[j] += __shfl_xor_sync(0xffffffffu, d[j], o);
        #pragma unroll
        for (int j = 0; j < 4; ++j) {
            float logit = d[j] * scale;
            float mn = fmaxf(m, logit);
            float c = __expf(m - mn), pe = __expf(logit - mn);
            l = l * c + pe;
            A.x = A.x*c + pe*V[j].x; A.y = A.y*c + pe*V[j].y;
            A.z = A.z*c + pe*V[j].z; A.w = A.w*c + pe*V[j].w;
            m = mn;
        }
    }
    for (; p < end; ++p) {
        int s = g_srcs[p];
        float4 k0 = *(const float4*)(g_k2 + (size_t)s * EMB + 4 * lane);
        float4 v0 = *(const float4*)(g_v2 + (size_t)s * EMB + 4 * lane);
        float d0 = qv.x*k0.x + qv.y*k0.y + qv.z*k0.z + qv.w*k0.w;
        #pragma unroll
        for (int o = 16; o; o >>= 1) d0 += __shfl_xor_sync(0xffffffffu, d0, o);
        float logit = d0 * scale;
        float mn = fmaxf(m, logit);
        float c = __expf(m - mn), pe = __expf(logit - mn);
        l = l * c + pe;
        A.x = A.x*c + pe*v0.x; A.y = A.y*c + pe*v0.y;
        A.z = A.z*c + pe*v0.z; A.w = A.w*c + pe*v0.w;
        m = mn;
    }
    if (l > 0.0f) {
        float inv = 1.0f / l;
        float4 o = *(float4*)(g_o2 + base);
        o.x += A.x*inv; o.y += A.y*inv; o.z += A.z*inv; o.w += A.w*inv;
        *(float4*)(g_o2 + base) = o;
    }
}

// ---------------- final mean over nodes (reads g_o2) -------------------------
__global__ void reduce_mean_kernel(float* __restrict__ out, int n) {
    int col = threadIdx.x;   // 128 threads
    float s = 0.0f;
    for (int r = blockIdx.x; r < n; r += gridDim.x)
        s += g_o2[(size_t)r * EMB + col];
    atomicAdd(&out[col], s * (1.0f / (float)n));
}

// ---------------- launch -----------------------------------------------------
extern "C" void kernel_launch(void* const* d_in, const int* in_sizes, int n_in,
                              void* d_out, int out_size)
{
    const float* x  = (const float*)d_in[0];
    const void*  ei = d_in[1];
    const float *Wq1 = (const float*)d_in[2],  *bq1 = (const float*)d_in[3];
    const float *Wk1 = (const float*)d_in[4],  *bk1 = (const float*)d_in[5];
    const float *Wv1 = (const float*)d_in[6],  *bv1 = (const float*)d_in[7];
    const float *Ws1 = (const float*)d_in[8],  *bs1 = (const float*)d_in[9];
    const float *Wq2 = (const float*)d_in[10], *bq2 = (const float*)d_in[11];
    const float *Wk2 = (const float*)d_in[12], *bk2 = (const float*)d_in[13];
    const float *Wv2 = (const float*)d_in[14], *bv2 = (const float*)d_in[15];
    const float *Ws2 = (const float*)d_in[16], *bs2 = (const float*)d_in[17];
    float* out = (float*)d_out;

    const int n = in_sizes[0] / INC;   // 50000
    const int e = in_sizes[1] / 2;     // 800000

    cudaFuncSetAttribute(mma_gemm_kernel,
                         cudaFuncAttributeMaxDynamicSharedMemorySize, GEMM_SMEM_BYTES);

    // ---- init (+dtype detect) + CSR build (by dst) ----
    {
        int threads = 256;
        init_kernel<<<(n + threads - 1) / threads, threads>>>(ei, out, n);
        hist_kernel<<<(e + threads - 1) / threads, threads>>>(ei, e, n);
        int nchunks = (n + 511) / 512;
        scanA_kernel<<<nchunks, 512>>>(n);
        scanB_kernel<<<1, 32>>>(nchunks);
        scanC_kernel<<<(n + threads - 1) / threads, threads>>>(n);
        scatter_kernel<<<(e + threads - 1) / threads, threads>>>(ei, e, n);
    }

    // ---- input splits ----
    {
        int totx = n * INC;
        xsplit_kernel<<<(totx + 255) / 256, 256>>>(x, totx);
        wsplit_kernel<<<1024, 256>>>(Wq1, Wk1, Wv1, Ws1, Wq2, Wk2, Wv2, Ws2);
    }

    int mtiles = (n + 127) / 128;

    // ---- layer 1 projections ----
    {
        dim3 grid(8, mtiles);
        mma_gemm_kernel<<<grid, 256, GEMM_SMEM_BYTES>>>(bq1, bk1, bv1, bs1,
                                                        n, INC, 2, 0, 0, 0);
    }

    // ---- layer 1 attention (fused skip+attn+relu+split -> g_hh/g_hl) ----
    {
        int blocks = (n + 7) / 8;
        attn1_kernel<<<blocks, 256>>>(n);
    }

    // ---- layer 2 projections ----
    {
        dim3 grid(4, mtiles);
        mma_gemm_kernel<<<grid, 256, GEMM_SMEM_BYTES>>>(bq2, bk2, bv2, bs2,
                                                        n, D1, 1, 131072, 1, 4);
    }

    // ---- layer 2 attention (adds into g_o2) ----
    {
        int blocks = (n + 7) / 8;
        attn2_kernel<<<blocks, 256>>>(n);
    }

    // ---- final mean over nodes ----
    reduce_mean_kernel<<<256, EMB>>>(out, n);
}

// round 8
// speedup vs baseline: 2.7413x; 1.2300x over previous
#include <cuda_runtime.h>
#include <cuda_bf16.h>
#include <cuda_fp16.h>
#include <math.h>
#include <stdint.h>

// Problem constants (fixed by the dataset)
#define NN 50000
#define EE 800000
#define INC 128
#define D1 256     // HID*HEADS
#define EMB 128

// ---------------- scratch (device globals; no allocation allowed) ------------
__device__ float g_q1[NN * D1];
__device__ float g_h [NN * D1];   // layer1 skip (from GEMM)
__device__ float g_q2[NN * EMB];
__device__ float g_o2[NN * EMB];  // layer2 skip + attention out

// fp16 k/v (gather-bandwidth halving)
__device__ __half g_k1h[NN * D1];
__device__ __half g_v1h[NN * D1];
__device__ __half g_k2h[NN * EMB];
__device__ __half g_v2h[NN * EMB];

// bf16 hi/lo splits for tensor-core GEMM inputs
__device__ __nv_bfloat16 g_xh[NN * INC];
__device__ __nv_bfloat16 g_xl[NN * INC];
__device__ __nv_bfloat16 g_hh[NN * D1];
__device__ __nv_bfloat16 g_hl[NN * D1];
// transposed+split weights: layer1 at [0, 131072), layer2 at [131072, 262144).
__device__ __nv_bfloat16 g_wh[262144];
__device__ __nv_bfloat16 g_wl[262144];

__device__ int g_deg   [NN];
__device__ int g_cursor[NN];
__device__ int g_incl  [NN];
__device__ int g_offs  [NN + 1];
__device__ int g_part  [128];
__device__ int g_cbase [128];
__device__ int g_srcs  [EE];
__device__ int g_is64;            // 1 if edge_index is int64, 0 if int32

// fp32 output selector (sels 0,3,4,7)
__device__ __forceinline__ float* buf_f32(int sel) {
    switch (sel) {
        case 0: return g_q1;
        case 3: return g_h;
        case 4: return g_q2;
        default: return g_o2;
    }
}
// fp16 output selector (sels 1,2,5,6)
__device__ __forceinline__ __half* buf_f16(int sel) {
    switch (sel) {
        case 1: return g_k1h;
        case 2: return g_v1h;
        case 5: return g_k2h;
        default: return g_v2h;
    }
}

__device__ __forceinline__ int edge_val(const void* ei, long long idx) {
    if (g_is64) return (int)((const long long*)ei)[idx];
    return ((const int*)ei)[idx];
}

__device__ __forceinline__ uint32_t smem_u32(const void* p) {
    uint32_t a;
    asm("{ .reg .u64 t; cvta.to.shared.u64 t, %1; cvt.u32.u64 %0, t; }"
        : "=r"(a) : "l"(p));
    return a;
}

__device__ __forceinline__ void ldsm4(uint32_t* r, uint32_t addr) {
    asm volatile("ldmatrix.sync.aligned.m8n8.x4.shared.b16 {%0,%1,%2,%3}, [%4];"
                 : "=r"(r[0]), "=r"(r[1]), "=r"(r[2]), "=r"(r[3]) : "r"(addr));
}

__device__ __forceinline__ void mma_bf16(float* d, const uint32_t* a,
                                         uint32_t b0, uint32_t b1) {
    asm volatile(
        "mma.sync.aligned.m16n8k16.row.col.f32.bf16.bf16.f32 "
        "{%0,%1,%2,%3}, {%4,%5,%6,%7}, {%8,%9}, {%0,%1,%2,%3};"
        : "+f"(d[0]), "+f"(d[1]), "+f"(d[2]), "+f"(d[3])
        : "r"(a[0]), "r"(a[1]), "r"(a[2]), "r"(a[3]), "r"(b0), "r"(b1));
}

__device__ __forceinline__ void cpasync16(uint32_t dst, const void* src, int sz) {
    asm volatile("cp.async.cg.shared.global [%0], [%1], 16, %2;"
                 :: "r"(dst), "l"(src), "r"(sz) : "memory");
}

// ---------------- init (+ edge dtype detection) ------------------------------
__global__ void init_kernel(const void* ei, float* out, int n) {
    int i = blockIdx.x * blockDim.x + threadIdx.x;
    if (i < n) { g_deg[i] = 0; g_cursor[i] = 0; }
    if (i < EMB) out[i] = 0.0f;
    if (i == 0) {
        g_offs[0] = 0;
        const long long* p = (const long long*)ei;
        int ok = 1;
        for (int j = 0; j < 32; ++j) {
            long long v = p[j];
            if (v < 0 || v >= n) ok = 0;
        }
        g_is64 = ok;
    }
}

// ---------------- CSR build -------------------------------------------------
__global__ void hist_kernel(const void* __restrict__ ei, int e, int n) {
    int idx = blockIdx.x * blockDim.x + threadIdx.x;
    if (idx < e) {
        int d = edge_val(ei, (long long)e + idx);
        if (d >= 0 && d < n) atomicAdd(&g_deg[d], 1);
    }
}

__global__ void scanA_kernel(int n) {
    __shared__ int s[512];
    int t = threadIdx.x;
    int i = blockIdx.x * 512 + t;
    int v = (i < n) ? g_deg[i] : 0;
    s[t] = v;
    __syncthreads();
    #pragma unroll
    for (int off = 1; off < 512; off <<= 1) {
        int add = (t >= off) ? s[t - off] : 0;
        __syncthreads();
        s[t] += add;
        __syncthreads();
    }
    if (i < n) g_incl[i] = s[t];
    if (t == 511) g_part[blockIdx.x] = s[511];
}

// parallel exclusive scan over <=128 chunk totals, 1 block 128 threads
__global__ void scanB_kernel(int nchunks) {
    __shared__ int s[128];
    int t = threadIdx.x;
    int v = (t < nchunks) ? g_part[t] : 0;
    s[t] = v;
    __syncthreads();
    #pragma unroll
    for (int off = 1; off < 128; off <<= 1) {
        int add = (t >= off) ? s[t - off] : 0;
        __syncthreads();
        s[t] += add;
        __syncthreads();
    }
    if (t < nchunks) g_cbase[t] = s[t] - v;   // exclusive
}

__global__ void scanC_kernel(int n) {
    int i = blockIdx.x * blockDim.x + threadIdx.x;
    if (i < n) g_offs[i + 1] = g_cbase[i >> 9] + g_incl[i];
}

__global__ void scatter_kernel(const void* __restrict__ ei, int e, int n) {
    int idx = blockIdx.x * blockDim.x + threadIdx.x;
    if (idx < e) {
        int d = edge_val(ei, (long long)e + idx);
        int s = edge_val(ei, idx);
        if (d >= 0 && d < n && s >= 0 && s < n) {
            int pos = g_offs[d] + atomicAdd(&g_cursor[d], 1);
            g_srcs[pos] = s;
        }
    }
}

// ---------------- bf16 split passes ------------------------------------------
__global__ void xsplit_kernel(const float* __restrict__ x, int total) {
    int i = blockIdx.x * blockDim.x + threadIdx.x;
    if (i < total) {
        float v = x[i];
        __nv_bfloat16 hi = __float2bfloat16(v);
        g_xh[i] = hi;
        g_xl[i] = __float2bfloat16(v - __bfloat162float(hi));
    }
}

__global__ void wsplit_kernel(const float* w0, const float* w1, const float* w2, const float* w3,
                              const float* w4, const float* w5, const float* w6, const float* w7) {
    int tid = blockIdx.x * blockDim.x + threadIdx.x;
    if (tid >= 262144) return;
    float v;
    int idx;
    if (tid < 131072) {
        int m = tid >> 15, r = tid & 32767;
        int n = r >> 7, k = r & 127;
        const float* W = (m == 0) ? w0 : (m == 1) ? w1 : (m == 2) ? w2 : w3;
        v = W[k * 256 + n];
        idx = m * 32768 + n * 128 + k;
    } else {
        int e = tid - 131072;
        int m = e >> 15, r = e & 32767;
        int n = r >> 8, k = r & 255;
        const float* W = (m == 0) ? w4 : (m == 1) ? w5 : (m == 2) ? w6 : w7;
        v = W[k * 128 + n];
        idx = 131072 + m * 32768 + n * 256 + k;
    }
    __nv_bfloat16 hi = __float2bfloat16(v);
    g_wh[idx] = hi;
    g_wl[idx] = __float2bfloat16(v - __bfloat162float(hi));
}

// ---------------- mma.sync GEMM with 2-stage cp.async pipeline ----------------
#define BK 32
#define LDT 40
#define TILE_ELEMS (128 * LDT)
#define STAGE_ELEMS (4 * TILE_ELEMS)
#define GEMM_SMEM_BYTES (2 * STAGE_ELEMS * 2)

__global__ __launch_bounds__(256, 2)
void mma_gemm_kernel(const float* __restrict__ b0, const float* __restrict__ b1,
                     const float* __restrict__ b2, const float* __restrict__ b3,
                     int M, int K, int ntiles, int wt_base, int layer, int out_base)
{
    extern __shared__ __align__(16) __nv_bfloat16 sm[];

    int tid = threadIdx.x, wid = tid >> 5, lane = tid & 31;
    int mat = blockIdx.x / ntiles, nt0 = blockIdx.x % ntiles;
    int m0 = blockIdx.y * 128;
    int n0 = nt0 * 128;
    int Ntot = ntiles * 128;

    const __nv_bfloat16* Ah = layer ? g_hh : g_xh;
    const __nv_bfloat16* Al = layer ? g_hl : g_xl;
    const __nv_bfloat16* Bh = g_wh + wt_base + mat * 32768;
    const __nv_bfloat16* Bl = g_wl + wt_base + mat * 32768;
    const float* bias = (mat == 0) ? b0 : (mat == 1) ? b1 : (mat == 2) ? b2 : b3;
    int osel = out_base + mat;
    bool is_half = (osel == 1 || osel == 2 || osel == 5 || osel == 6);

    int warp_m = wid >> 1;
    int warp_n = wid & 1;

    float acc[2][8][4];
    #pragma unroll
    for (int i = 0; i < 2; ++i)
        #pragma unroll
        for (int j = 0; j < 8; ++j)
            #pragma unroll
            for (int q = 0; q < 4; ++q) acc[i][j][q] = 0.0f;

    uint32_t smu = smem_u32(sm);
    int nchunks = K / BK;

    auto issue = [&](int kc) {
        int kb = kc * BK;
        uint32_t sbase = smu + (uint32_t)(kc & 1) * (STAGE_ELEMS * 2);
        #pragma unroll
        for (int it = 0; it < 8; ++it) {
            int i = tid + it * 256;
            int t = i >> 9, w = i & 511;
            int row = w >> 2, c8 = (w & 3) * 8;
            uint32_t dst = sbase + (uint32_t)(t * TILE_ELEMS + row * LDT + c8) * 2;
            if (t < 2) {
                int r = m0 + row;
                const __nv_bfloat16* src = (t == 0 ? Ah : Al);
                const void* sp = (r < M) ? (const void*)(src + (size_t)r * K + kb + c8)
                                         : (const void*)src;
                cpasync16(dst, sp, (r < M) ? 16 : 0);
            } else {
                const __nv_bfloat16* Bp = (t == 2) ? Bh : Bl;
                cpasync16(dst, Bp + (size_t)(n0 + row) * K + kb + c8, 16);
            }
        }
        asm volatile("cp.async.commit_group;" ::: "memory");
    };

    uint32_t a_row = warp_m * 32 + (lane & 15);
    uint32_t a_koff = (lane >> 4) * 8;
    uint32_t b_nrow = warp_n * 64 + (lane & 7) + ((lane >> 3) & 1) * 8;
    uint32_t b_koff = (lane >> 4) * 8;

    issue(0);

    for (int kc = 0; kc < nchunks; ++kc) {
        if (kc + 1 < nchunks) {
            issue(kc + 1);
            asm volatile("cp.async.wait_group 1;" ::: "memory");
        } else {
            asm volatile("cp.async.wait_group 0;" ::: "memory");
        }
        __syncthreads();

        uint32_t sbase = smu + (uint32_t)(kc & 1) * (STAGE_ELEMS * 2);
        uint32_t sAh_u = sbase;
        uint32_t sAl_u = sbase + TILE_ELEMS * 2;
        uint32_t sBh_u = sbase + 2 * TILE_ELEMS * 2;
        uint32_t sBl_u = sbase + 3 * TILE_ELEMS * 2;

        #pragma unroll
        for (int ks = 0; ks < BK / 16; ++ks) {
            uint32_t aH[2][4], aL[2][4], bH[4][4], bL[4][4];
            #pragma unroll
            for (int mt = 0; mt < 2; ++mt) {
                uint32_t off = ((a_row + mt * 16) * LDT + ks * 16 + a_koff) * 2;
                ldsm4(aH[mt], sAh_u + off);
                ldsm4(aL[mt], sAl_u + off);
            }
            #pragma unroll
            for (int nb = 0; nb < 4; ++nb) {
                uint32_t off = ((b_nrow + nb * 16) * LDT + ks * 16 + b_koff) * 2;
                ldsm4(bH[nb], sBh_u + off);
                ldsm4(bL[nb], sBl_u + off);
            }
            #pragma unroll
            for (int mt = 0; mt < 2; ++mt) {
                #pragma unroll
                for (int j = 0; j < 8; ++j) {
                    int nb = j >> 1, par = j & 1;
                    mma_bf16(acc[mt][j], aH[mt], bH[nb][par], bH[nb][par + 2]);
                    mma_bf16(acc[mt][j], aH[mt], bL[nb][par], bL[nb][par + 2]);
                    mma_bf16(acc[mt][j], aL[mt], bH[nb][par], bH[nb][par + 2]);
                }
            }
        }
        __syncthreads();
    }

    if (is_half) {
        __half* Ch = buf_f16(osel);
        #pragma unroll
        for (int mt = 0; mt < 2; ++mt) {
            int r0 = m0 + warp_m * 32 + mt * 16 + (lane >> 2);
            #pragma unroll
            for (int j = 0; j < 8; ++j) {
                int c = n0 + warp_n * 64 + j * 8 + (lane & 3) * 2;
                float2 bv = *(const float2*)(bias + c);
                if (r0 < M) {
                    __half2 o0 = __floats2half2_rn(acc[mt][j][0] + bv.x,
                                                   acc[mt][j][1] + bv.y);
                    *(__half2*)(Ch + (size_t)r0 * Ntot + c) = o0;
                }
                if (r0 + 8 < M) {
                    __half2 o1 = __floats2half2_rn(acc[mt][j][2] + bv.x,
                                                   acc[mt][j][3] + bv.y);
                    *(__half2*)(Ch + (size_t)(r0 + 8) * Ntot + c) = o1;
                }
            }
        }
    } else {
        float* C = buf_f32(osel);
        #pragma unroll
        for (int mt = 0; mt < 2; ++mt) {
            int r0 = m0 + warp_m * 32 + mt * 16 + (lane >> 2);
            #pragma unroll
            for (int j = 0; j < 8; ++j) {
                int c = n0 + warp_n * 64 + j * 8 + (lane & 3) * 2;
                float2 bv = *(const float2*)(bias + c);
                if (r0 < M) {
                    float2 o0 = make_float2(acc[mt][j][0] + bv.x, acc[mt][j][1] + bv.y);
                    *(float2*)(C + (size_t)r0 * Ntot + c) = o0;
                }
                if (r0 + 8 < M) {
                    float2 o1 = make_float2(acc[mt][j][2] + bv.x, acc[mt][j][3] + bv.y);
                    *(float2*)(C + (size_t)(r0 + 8) * Ntot + c) = o1;
                }
            }
        }
    }
}

// unpack 8 halves (uint4) -> 8 floats
__device__ __forceinline__ void h8_to_f8(uint4 u, float* f) {
    union { uint4 u; __half2 h[4]; } c;
    c.u = u;
    #pragma unroll
    for (int j = 0; j < 4; ++j) {
        float2 p = __half22float2(c.h[j]);
        f[2 * j] = p.x;
        f[2 * j + 1] = p.y;
    }
}

// ---------------- attention layer 1 (fused skip+attn+relu+split) -------------
// warp per node, 4 heads via lane groups of 8; each lane owns 8 floats.
// k/v gathered in fp16 (one uint4 per row-slice). unroll 4.
__global__ void attn1_kernel(int n)
{
    int node = (blockIdx.x * blockDim.x + threadIdx.x) >> 5;
    int lane = threadIdx.x & 31;
    if (node >= n) return;

    int off = (lane >> 3) * 64 + (lane & 7) * 8;
    const float* qb = g_q1 + (size_t)node * D1 + off;
    float4 q0 = *(const float4*)qb;
    float4 q1 = *(const float4*)(qb + 4);
    float qf[8] = { q0.x, q0.y, q0.z, q0.w, q1.x, q1.y, q1.z, q1.w };

    float m = -1e30f, l = 0.0f;
    float A[8] = { 0.f, 0.f, 0.f, 0.f, 0.f, 0.f, 0.f, 0.f };

    int beg = g_offs[node], end = g_offs[node + 1];
    int p = beg;
    for (; p + 4 <= end; p += 4) {
        uint4 kr[4], vr[4];
        #pragma unroll
        for (int j = 0; j < 4; ++j) {
            int s = g_srcs[p + j];
            kr[j] = *(const uint4*)(g_k1h + (size_t)s * D1 + off);
            vr[j] = *(const uint4*)(g_v1h + (size_t)s * D1 + off);
        }
        float d[4];
        #pragma unroll
        for (int j = 0; j < 4; ++j) {
            float kf[8];
            h8_to_f8(kr[j], kf);
            float t = 0.f;
            #pragma unroll
            for (int q = 0; q < 8; ++q) t += qf[q] * kf[q];
            d[j] = t;
        }
        #pragma unroll
        for (int o = 4; o; o >>= 1)
            #pragma unroll
            for (int j = 0; j < 4; ++j)
                d[j] += __shfl_xor_sync(0xffffffffu, d[j], o);
        #pragma unroll
        for (int j = 0; j < 4; ++j) {
            float logit = d[j] * 0.125f;
            float mn = fmaxf(m, logit);
            float c = __expf(m - mn), pe = __expf(logit - mn);
            l = l * c + pe;
            float vf[8];
            h8_to_f8(vr[j], vf);
            #pragma unroll
            for (int q = 0; q < 8; ++q) A[q] = A[q] * c + pe * vf[q];
            m = mn;
        }
    }
    for (; p < end; ++p) {
        int s = g_srcs[p];
        uint4 kr = *(const uint4*)(g_k1h + (size_t)s * D1 + off);
        uint4 vr = *(const uint4*)(g_v1h + (size_t)s * D1 + off);
        float kf[8];
        h8_to_f8(kr, kf);
        float d0 = 0.f;
        #pragma unroll
        for (int q = 0; q < 8; ++q) d0 += qf[q] * kf[q];
        #pragma unroll
        for (int o = 4; o; o >>= 1) d0 += __shfl_xor_sync(0xffffffffu, d0, o);
        float logit = d0 * 0.125f;
        float mn = fmaxf(m, logit);
        float c = __expf(m - mn), pe = __expf(logit - mn);
        l = l * c + pe;
        float vf[8];
        h8_to_f8(vr, vf);
        #pragma unroll
        for (int q = 0; q < 8; ++q) A[q] = A[q] * c + pe * vf[q];
        m = mn;
    }

    float inv = (l > 0.0f) ? 1.0f / l : 0.0f;
    const float* hb = g_h + (size_t)node * D1 + off;
    float4 h0 = *(const float4*)hb;
    float4 h1 = *(const float4*)(hb + 4);
    float hv[8] = { h0.x, h0.y, h0.z, h0.w, h1.x, h1.y, h1.z, h1.w };

    union { uint4 u; __nv_bfloat16 b[8]; } hi_u, lo_u;
    #pragma unroll
    for (int j = 0; j < 8; ++j) {
        float v = fmaxf(hv[j] + A[j] * inv, 0.0f);
        __nv_bfloat16 hi = __float2bfloat16(v);
        hi_u.b[j] = hi;
        lo_u.b[j] = __float2bfloat16(v - __bfloat162float(hi));
    }
    *(uint4*)(g_hh + (size_t)node * D1 + off) = hi_u.u;
    *(uint4*)(g_hl + (size_t)node * D1 + off) = lo_u.u;
}

// ---------------- attention layer 2: 1 head, d=128, warp per node, unroll 4 --
__global__ void attn2_kernel(int n)
{
    int node = (blockIdx.x * blockDim.x + threadIdx.x) >> 5;
    int lane = threadIdx.x & 31;
    if (node >= n) return;

    int base = node * EMB + 4 * lane;
    float4 qv = *(const float4*)(g_q2 + base);

    float m = -1e30f, l = 0.0f;
    float4 A = make_float4(0.f, 0.f, 0.f, 0.f);
    int beg = g_offs[node], end = g_offs[node + 1];
    const float scale = 0.088388347648318447f;   // 1/sqrt(128)

    int p = beg;
    for (; p + 4 <= end; p += 4) {
        uint2 kr[4], vr[4];
        #pragma unroll
        for (int j = 0; j < 4; ++j) {
            int s = g_srcs[p + j];
            kr[j] = *(const uint2*)(g_k2h + (size_t)s * EMB + 4 * lane);
            vr[j] = *(const uint2*)(g_v2h + (size_t)s * EMB + 4 * lane);
        }
        float d[4];
        #pragma unroll
        for (int j = 0; j < 4; ++j) {
            union { uint2 u; __half2 h[2]; } c;
            c.u = kr[j];
            float2 p0 = __half22float2(c.h[0]);
            float2 p1 = __half22float2(c.h[1]);
            d[j] = qv.x * p0.x + qv.y * p0.y + qv.z * p1.x + qv.w * p1.y;
        }
        #pragma unroll
        for (int o = 16; o; o >>= 1)
            #pragma unroll
            for (int j = 0; j < 4; ++j)
                d[j] += __shfl_xor_sync(0xffffffffu, d[j], o);
        #pragma unroll
        for (int j = 0; j < 4; ++j) {
            float logit = d[j] * scale;
            float mn = fmaxf(m, logit);
            float c = __expf(m - mn), pe = __expf(logit - mn);
            l = l * c + pe;
            union { uint2 u; __half2 h[2]; } cv;
            cv.u = vr[j];
            float2 v0 = __half22float2(cv.h[0]);
            float2 v1 = __half22float2(cv.h[1]);
            A.x = A.x * c + pe * v0.x; A.y = A.y * c + pe * v0.y;
            A.z = A.z * c + pe * v1.x; A.w = A.w * c + pe * v1.y;
            m = mn;
        }
    }
    for (; p < end; ++p) {
        int s = g_srcs[p];
        union { uint2 u; __half2 h[2]; } ck, cv;
        ck.u = *(const uint2*)(g_k2h + (size_t)s * EMB + 4 * lane);
        cv.u = *(const uint2*)(g_v2h + (size_t)s * EMB + 4 * lane);
        float2 p0 = __half22float2(ck.h[0]);
        float2 p1 = __half22float2(ck.h[1]);
        float d0 = qv.x * p0.x + qv.y * p0.y + qv.z * p1.x + qv.w * p1.y;
        #pragma unroll
        for (int o = 16; o; o >>= 1) d0 += __shfl_xor_sync(0xffffffffu, d0, o);
        float logit = d0 * scale;
        float mn = fmaxf(m, logit);
        float c = __expf(m - mn), pe = __expf(logit - mn);
        l = l * c + pe;
        float2 v0 = __half22float2(cv.h[0]);
        float2 v1 = __half22float2(cv.h[1]);
        A.x = A.x * c + pe * v0.x; A.y = A.y * c + pe * v0.y;
        A.z = A.z * c + pe * v1.x; A.w = A.w * c + pe * v1.y;
        m = mn;
    }
    if (l > 0.0f) {
        float inv = 1.0f / l;
        float4 o = *(float4*)(g_o2 + base);
        o.x += A.x * inv; o.y += A.y * inv; o.z += A.z * inv; o.w += A.w * inv;
        *(float4*)(g_o2 + base) = o;
    }
}

// ---------------- final mean over nodes (reads g_o2) -------------------------
__global__ void reduce_mean_kernel(float* __restrict__ out, int n) {
    int col = threadIdx.x;   // 128 threads
    float s = 0.0f;
    for (int r = blockIdx.x; r < n; r += gridDim.x)
        s += g_o2[(size_t)r * EMB + col];
    atomicAdd(&out[col], s * (1.0f / (float)n));
}

// ---------------- launch -----------------------------------------------------
extern "C" void kernel_launch(void* const* d_in, const int* in_sizes, int n_in,
                              void* d_out, int out_size)
{
    const float* x  = (const float*)d_in[0];
    const void*  ei = d_in[1];
    const float *Wq1 = (const float*)d_in[2],  *bq1 = (const float*)d_in[3];
    const float *Wk1 = (const float*)d_in[4],  *bk1 = (const float*)d_in[5];
    const float *Wv1 = (const float*)d_in[6],  *bv1 = (const float*)d_in[7];
    const float *Ws1 = (const float*)d_in[8],  *bs1 = (const float*)d_in[9];
    const float *Wq2 = (const float*)d_in[10], *bq2 = (const float*)d_in[11];
    const float *Wk2 = (const float*)d_in[12], *bk2 = (const float*)d_in[13];
    const float *Wv2 = (const float*)d_in[14], *bv2 = (const float*)d_in[15];
    const float *Ws2 = (const float*)d_in[16], *bs2 = (const float*)d_in[17];
    float* out = (float*)d_out;

    const int n = in_sizes[0] / INC;   // 50000
    const int e = in_sizes[1] / 2;     // 800000

    cudaFuncSetAttribute(mma_gemm_kernel,
                         cudaFuncAttributeMaxDynamicSharedMemorySize, GEMM_SMEM_BYTES);

    // ---- init (+dtype detect) + CSR build (by dst) ----
    {
        int threads = 256;
        init_kernel<<<(n + threads - 1) / threads, threads>>>(ei, out, n);
        hist_kernel<<<(e + threads - 1) / threads, threads>>>(ei, e, n);
        int nchunks = (n + 511) / 512;
        scanA_kernel<<<nchunks, 512>>>(n);
        scanB_kernel<<<1, 128>>>(nchunks);
        scanC_kernel<<<(n + threads - 1) / threads, threads>>>(n);
        scatter_kernel<<<(e + threads - 1) / threads, threads>>>(ei, e, n);
    }

    // ---- input splits ----
    {
        int totx = n * INC;
        xsplit_kernel<<<(totx + 255) / 256, 256>>>(x, totx);
        wsplit_kernel<<<1024, 256>>>(Wq1, Wk1, Wv1, Ws1, Wq2, Wk2, Wv2, Ws2);
    }

    int mtiles = (n + 127) / 128;

    // ---- layer 1 projections (q1 fp32, k1/v1 fp16, h fp32) ----
    {
        dim3 grid(8, mtiles);
        mma_gemm_kernel<<<grid, 256, GEMM_SMEM_BYTES>>>(bq1, bk1, bv1, bs1,
                                                        n, INC, 2, 0, 0, 0);
    }

    // ---- layer 1 attention (fused skip+attn+relu+split -> g_hh/g_hl) ----
    {
        int blocks = (n + 7) / 8;
        attn1_kernel<<<blocks, 256>>>(n);
    }

    // ---- layer 2 projections (q2 fp32, k2/v2 fp16, o2 fp32) ----
    {
        dim3 grid(4, mtiles);
        mma_gemm_kernel<<<grid, 256, GEMM_SMEM_BYTES>>>(bq2, bk2, bv2, bs2,
                                                        n, D1, 1, 131072, 1, 4);
    }

    // ---- layer 2 attention (adds into g_o2) ----
    {
        int blocks = (n + 7) / 8;
        attn2_kernel<<<blocks, 256>>>(n);
    }

    // ---- final mean over nodes ----
    reduce_mean_kernel<<<256, EMB>>>(out, n);
}

// round 9
// speedup vs baseline: 3.2421x; 1.1827x over previous
#include <cuda_runtime.h>
#include <cuda_bf16.h>
#include <cuda_fp16.h>
#include <math.h>
#include <stdint.h>

// Problem constants (fixed by the dataset)
#define NN 50000
#define EE 800000
#define INC 128
#define D1 256     // HID*HEADS
#define EMB 128

// ---------------- scratch (device globals; no allocation allowed) ------------
__device__ float g_q1[NN * D1];
__device__ float g_h [NN * D1];   // layer1 skip (from GEMM)
__device__ float g_q2[NN * EMB];
__device__ float g_o2[NN * EMB];  // layer2 skip + attention out

// fp16 k/v (gather-bandwidth halving)
__device__ __half g_k1h[NN * D1];
__device__ __half g_v1h[NN * D1];
__device__ __half g_k2h[NN * EMB];
__device__ __half g_v2h[NN * EMB];

// fp16 activations for GEMM A operand
__device__ __half g_xf[NN * INC];
__device__ __half g_hf[NN * D1];
// transposed fp16 hi/lo weights: layer1 at [0,131072), layer2 at [131072,262144).
// Layout: Wt[n][k] row-major.
__device__ __half g_wh[262144];
__device__ __half g_wl[262144];

__device__ int g_deg   [NN];
__device__ int g_cursor[NN];
__device__ int g_incl  [NN];
__device__ int g_offs  [NN + 1];
__device__ int g_part  [128];
__device__ int g_cbase [128];
__device__ int g_srcs  [EE];
__device__ int g_is64;            // 1 if edge_index is int64, 0 if int32

// fp32 output selector (sels 0,3,4,7)
__device__ __forceinline__ float* buf_f32(int sel) {
    switch (sel) {
        case 0: return g_q1;
        case 3: return g_h;
        case 4: return g_q2;
        default: return g_o2;
    }
}
// fp16 output selector (sels 1,2,5,6)
__device__ __forceinline__ __half* buf_f16(int sel) {
    switch (sel) {
        case 1: return g_k1h;
        case 2: return g_v1h;
        case 5: return g_k2h;
        default: return g_v2h;
    }
}

__device__ __forceinline__ int edge_val(const void* ei, long long idx) {
    if (g_is64) return (int)((const long long*)ei)[idx];
    return ((const int*)ei)[idx];
}

__device__ __forceinline__ uint32_t smem_u32(const void* p) {
    uint32_t a;
    asm("{ .reg .u64 t; cvta.to.shared.u64 t, %1; cvt.u32.u64 %0, t; }"
        : "=r"(a) : "l"(p));
    return a;
}

__device__ __forceinline__ void ldsm4(uint32_t* r, uint32_t addr) {
    asm volatile("ldmatrix.sync.aligned.m8n8.x4.shared.b16 {%0,%1,%2,%3}, [%4];"
                 : "=r"(r[0]), "=r"(r[1]), "=r"(r[2]), "=r"(r[3]) : "r"(addr));
}

// mma m16n8k16 fp16 -> fp32 accumulate
__device__ __forceinline__ void mma_f16(float* d, const uint32_t* a,
                                        uint32_t b0, uint32_t b1) {
    asm volatile(
        "mma.sync.aligned.m16n8k16.row.col.f32.f16.f16.f32 "
        "{%0,%1,%2,%3}, {%4,%5,%6,%7}, {%8,%9}, {%0,%1,%2,%3};"
        : "+f"(d[0]), "+f"(d[1]), "+f"(d[2]), "+f"(d[3])
        : "r"(a[0]), "r"(a[1]), "r"(a[2]), "r"(a[3]), "r"(b0), "r"(b1));
}

__device__ __forceinline__ void cpasync16(uint32_t dst, const void* src, int sz) {
    asm volatile("cp.async.cg.shared.global [%0], [%1], 16, %2;"
                 :: "r"(dst), "l"(src), "r"(sz) : "memory");
}

// ---------------- init (+ edge dtype detection) ------------------------------
__global__ void init_kernel(const void* ei, float* out, int n) {
    int i = blockIdx.x * blockDim.x + threadIdx.x;
    if (i < n) { g_deg[i] = 0; g_cursor[i] = 0; }
    if (i < EMB) out[i] = 0.0f;
    if (i == 0) {
        g_offs[0] = 0;
        const long long* p = (const long long*)ei;
        int ok = 1;
        for (int j = 0; j < 32; ++j) {
            long long v = p[j];
            if (v < 0 || v >= n) ok = 0;
        }
        g_is64 = ok;
    }
}

// ---------------- CSR build -------------------------------------------------
__global__ void hist_kernel(const void* __restrict__ ei, int e, int n) {
    int idx = blockIdx.x * blockDim.x + threadIdx.x;
    if (idx < e) {
        int d = edge_val(ei, (long long)e + idx);
        if (d >= 0 && d < n) atomicAdd(&g_deg[d], 1);
    }
}

__global__ void scanA_kernel(int n) {
    __shared__ int s[512];
    int t = threadIdx.x;
    int i = blockIdx.x * 512 + t;
    int v = (i < n) ? g_deg[i] : 0;
    s[t] = v;
    __syncthreads();
    #pragma unroll
    for (int off = 1; off < 512; off <<= 1) {
        int add = (t >= off) ? s[t - off] : 0;
        __syncthreads();
        s[t] += add;
        __syncthreads();
    }
    if (i < n) g_incl[i] = s[t];
    if (t == 511) g_part[blockIdx.x] = s[511];
}

__global__ void scanB_kernel(int nchunks) {
    __shared__ int s[128];
    int t = threadIdx.x;
    int v = (t < nchunks) ? g_part[t] : 0;
    s[t] = v;
    __syncthreads();
    #pragma unroll
    for (int off = 1; off < 128; off <<= 1) {
        int add = (t >= off) ? s[t - off] : 0;
        __syncthreads();
        s[t] += add;
        __syncthreads();
    }
    if (t < nchunks) g_cbase[t] = s[t] - v;   // exclusive
}

__global__ void scanC_kernel(int n) {
    int i = blockIdx.x * blockDim.x + threadIdx.x;
    if (i < n) g_offs[i + 1] = g_cbase[i >> 9] + g_incl[i];
}

__global__ void scatter_kernel(const void* __restrict__ ei, int e, int n) {
    int idx = blockIdx.x * blockDim.x + threadIdx.x;
    if (idx < e) {
        int d = edge_val(ei, (long long)e + idx);
        int s = edge_val(ei, idx);
        if (d >= 0 && d < n && s >= 0 && s < n) {
            int pos = g_offs[d] + atomicAdd(&g_cursor[d], 1);
            g_srcs[pos] = s;
        }
    }
}

// ---------------- conversion passes -------------------------------------------
__global__ void xconv_kernel(const float* __restrict__ x, int total) {
    int i = blockIdx.x * blockDim.x + threadIdx.x;
    if (i < total) g_xf[i] = __float2half_rn(x[i]);
}

// transpose + fp16 hi/lo split of all 8 weight matrices
__global__ void wsplit_kernel(const float* w0, const float* w1, const float* w2, const float* w3,
                              const float* w4, const float* w5, const float* w6, const float* w7) {
    int tid = blockIdx.x * blockDim.x + threadIdx.x;
    if (tid >= 262144) return;
    float v;
    int idx;
    if (tid < 131072) {
        int m = tid >> 15, r = tid & 32767;
        int n = r >> 7, k = r & 127;
        const float* W = (m == 0) ? w0 : (m == 1) ? w1 : (m == 2) ? w2 : w3;
        v = W[k * 256 + n];
        idx = m * 32768 + n * 128 + k;
    } else {
        int e = tid - 131072;
        int m = e >> 15, r = e & 32767;
        int n = r >> 8, k = r & 255;
        const float* W = (m == 0) ? w4 : (m == 1) ? w5 : (m == 2) ? w6 : w7;
        v = W[k * 128 + n];
        idx = 131072 + m * 32768 + n * 256 + k;
    }
    __half hi = __float2half_rn(v);
    g_wh[idx] = hi;
    g_wl[idx] = __float2half_rn(v - __half2float(hi));
}

// ---------------- mma.sync fp16 GEMM, 2-term, 2-stage cp.async ----------------
// C = A(fp16) @ (Wh + Wl)^T + bias. A[M,K], Wt[N,K]. fp32 accum.
#define BK 32
#define LDT 40
#define TILE_ELEMS (128 * LDT)
#define STAGE_ELEMS (3 * TILE_ELEMS)            // A, Bh, Bl
#define GEMM_SMEM_BYTES (2 * STAGE_ELEMS * 2)   // 61440 B

__global__ __launch_bounds__(256, 2)
void mma_gemm_kernel(const float* __restrict__ b0, const float* __restrict__ b1,
                     const float* __restrict__ b2, const float* __restrict__ b3,
                     int M, int K, int ntiles, int wt_base, int layer, int out_base)
{
    extern __shared__ __align__(16) __half sm[];

    int tid = threadIdx.x, wid = tid >> 5, lane = tid & 31;
    int mat = blockIdx.x / ntiles, nt0 = blockIdx.x % ntiles;
    int m0 = blockIdx.y * 128;
    int n0 = nt0 * 128;
    int Ntot = ntiles * 128;

    const __half* Af = layer ? g_hf : g_xf;
    const __half* Bh = g_wh + wt_base + mat * 32768;
    const __half* Bl = g_wl + wt_base + mat * 32768;
    const float* bias = (mat == 0) ? b0 : (mat == 1) ? b1 : (mat == 2) ? b2 : b3;
    int osel = out_base + mat;
    bool is_half = (osel == 1 || osel == 2 || osel == 5 || osel == 6);

    int warp_m = wid >> 1;
    int warp_n = wid & 1;

    float acc[2][8][4];
    #pragma unroll
    for (int i = 0; i < 2; ++i)
        #pragma unroll
        for (int j = 0; j < 8; ++j)
            #pragma unroll
            for (int q = 0; q < 4; ++q) acc[i][j][q] = 0.0f;

    uint32_t smu = smem_u32(sm);
    int nchunks = K / BK;

    // 1536 16B-chunks per stage: t=0 A, t=1 Bh, t=2 Bl
    auto issue = [&](int kc) {
        int kb = kc * BK;
        uint32_t sbase = smu + (uint32_t)(kc & 1) * (STAGE_ELEMS * 2);
        #pragma unroll
        for (int it = 0; it < 6; ++it) {
            int i = tid + it * 256;
            int t = i >> 9, w = i & 511;
            int row = w >> 2, c8 = (w & 3) * 8;
            uint32_t dst = sbase + (uint32_t)(t * TILE_ELEMS + row * LDT + c8) * 2;
            if (t == 0) {
                int r = m0 + row;
                const void* sp = (r < M) ? (const void*)(Af + (size_t)r * K + kb + c8)
                                         : (const void*)Af;
                cpasync16(dst, sp, (r < M) ? 16 : 0);
            } else {
                const __half* Bp = (t == 1) ? Bh : Bl;
                cpasync16(dst, Bp + (size_t)(n0 + row) * K + kb + c8, 16);
            }
        }
        asm volatile("cp.async.commit_group;" ::: "memory");
    };

    uint32_t a_row = warp_m * 32 + (lane & 15);
    uint32_t a_koff = (lane >> 4) * 8;
    uint32_t b_nrow = warp_n * 64 + (lane & 7) + ((lane >> 3) & 1) * 8;
    uint32_t b_koff = (lane >> 4) * 8;

    issue(0);

    for (int kc = 0; kc < nchunks; ++kc) {
        if (kc + 1 < nchunks) {
            issue(kc + 1);
            asm volatile("cp.async.wait_group 1;" ::: "memory");
        } else {
            asm volatile("cp.async.wait_group 0;" ::: "memory");
        }
        __syncthreads();

        uint32_t sbase = smu + (uint32_t)(kc & 1) * (STAGE_ELEMS * 2);
        uint32_t sA_u  = sbase;
        uint32_t sBh_u = sbase + TILE_ELEMS * 2;
        uint32_t sBl_u = sbase + 2 * TILE_ELEMS * 2;

        #pragma unroll
        for (int ks = 0; ks < BK / 16; ++ks) {
            uint32_t aF[2][4], bH[4][4], bL[4][4];
            #pragma unroll
            for (int mt = 0; mt < 2; ++mt) {
                uint32_t off = ((a_row + mt * 16) * LDT + ks * 16 + a_koff) * 2;
                ldsm4(aF[mt], sA_u + off);
            }
            #pragma unroll
            for (int nb = 0; nb < 4; ++nb) {
                uint32_t off = ((b_nrow + nb * 16) * LDT + ks * 16 + b_koff) * 2;
                ldsm4(bH[nb], sBh_u + off);
                ldsm4(bL[nb], sBl_u + off);
            }
            #pragma unroll
            for (int mt = 0; mt < 2; ++mt) {
                #pragma unroll
                for (int j = 0; j < 8; ++j) {
                    int nb = j >> 1, par = j & 1;
                    mma_f16(acc[mt][j], aF[mt], bH[nb][par], bH[nb][par + 2]);
                    mma_f16(acc[mt][j], aF[mt], bL[nb][par], bL[nb][par + 2]);
                }
            }
        }
        __syncthreads();
    }

    if (is_half) {
        __half* Ch = buf_f16(osel);
        #pragma unroll
        for (int mt = 0; mt < 2; ++mt) {
            int r0 = m0 + warp_m * 32 + mt * 16 + (lane >> 2);
            #pragma unroll
            for (int j = 0; j < 8; ++j) {
                int c = n0 + warp_n * 64 + j * 8 + (lane & 3) * 2;
                float2 bv = *(const float2*)(bias + c);
                if (r0 < M) {
                    __half2 o0 = __floats2half2_rn(acc[mt][j][0] + bv.x,
                                                   acc[mt][j][1] + bv.y);
                    *(__half2*)(Ch + (size_t)r0 * Ntot + c) = o0;
                }
                if (r0 + 8 < M) {
                    __half2 o1 = __floats2half2_rn(acc[mt][j][2] + bv.x,
                                                   acc[mt][j][3] + bv.y);
                    *(__half2*)(Ch + (size_t)(r0 + 8) * Ntot + c) = o1;
                }
            }
        }
    } else {
        float* C = buf_f32(osel);
        #pragma unroll
        for (int mt = 0; mt < 2; ++mt) {
            int r0 = m0 + warp_m * 32 + mt * 16 + (lane >> 2);
            #pragma unroll
            for (int j = 0; j < 8; ++j) {
                int c = n0 + warp_n * 64 + j * 8 + (lane & 3) * 2;
                float2 bv = *(const float2*)(bias + c);
                if (r0 < M) {
                    float2 o0 = make_float2(acc[mt][j][0] + bv.x, acc[mt][j][1] + bv.y);
                    *(float2*)(C + (size_t)r0 * Ntot + c) = o0;
                }
                if (r0 + 8 < M) {
                    float2 o1 = make_float2(acc[mt][j][2] + bv.x, acc[mt][j][3] + bv.y);
                    *(float2*)(C + (size_t)(r0 + 8) * Ntot + c) = o1;
                }
            }
        }
    }
}

// unpack 8 halves (uint4) -> 8 floats
__device__ __forceinline__ void h8_to_f8(uint4 u, float* f) {
    union { uint4 u; __half2 h[4]; } c;
    c.u = u;
    #pragma unroll
    for (int j = 0; j < 4; ++j) {
        float2 p = __half22float2(c.h[j]);
        f[2 * j] = p.x;
        f[2 * j + 1] = p.y;
    }
}

// ---------------- attention layer 1 (fused skip+attn+relu+fp16 conv) ---------
__global__ void attn1_kernel(int n)
{
    int node = (blockIdx.x * blockDim.x + threadIdx.x) >> 5;
    int lane = threadIdx.x & 31;
    if (node >= n) return;

    int off = (lane >> 3) * 64 + (lane & 7) * 8;
    const float* qb = g_q1 + (size_t)node * D1 + off;
    float4 q0 = *(const float4*)qb;
    float4 q1 = *(const float4*)(qb + 4);
    float qf[8] = { q0.x, q0.y, q0.z, q0.w, q1.x, q1.y, q1.z, q1.w };

    float m = -1e30f, l = 0.0f;
    float A[8] = { 0.f, 0.f, 0.f, 0.f, 0.f, 0.f, 0.f, 0.f };

    int beg = g_offs[node], end = g_offs[node + 1];
    int p = beg;
    for (; p + 4 <= end; p += 4) {
        uint4 kr[4], vr[4];
        #pragma unroll
        for (int j = 0; j < 4; ++j) {
            int s = g_srcs[p + j];
            kr[j] = *(const uint4*)(g_k1h + (size_t)s * D1 + off);
            vr[j] = *(const uint4*)(g_v1h + (size_t)s * D1 + off);
        }
        float d[4];
        #pragma unroll
        for (int j = 0; j < 4; ++j) {
            float kf[8];
            h8_to_f8(kr[j], kf);
            float t = 0.f;
            #pragma unroll
            for (int q = 0; q < 8; ++q) t += qf[q] * kf[q];
            d[j] = t;
        }
        #pragma unroll
        for (int o = 4; o; o >>= 1)
            #pragma unroll
            for (int j = 0; j < 4; ++j)
                d[j] += __shfl_xor_sync(0xffffffffu, d[j], o);
        #pragma unroll
        for (int j = 0; j < 4; ++j) {
            float logit = d[j] * 0.125f;
            float mn = fmaxf(m, logit);
            float c = __expf(m - mn), pe = __expf(logit - mn);
            l = l * c + pe;
            float vf[8];
            h8_to_f8(vr[j], vf);
            #pragma unroll
            for (int q = 0; q < 8; ++q) A[q] = A[q] * c + pe * vf[q];
            m = mn;
        }
    }
    for (; p < end; ++p) {
        int s = g_srcs[p];
        uint4 kr = *(const uint4*)(g_k1h + (size_t)s * D1 + off);
        uint4 vr = *(const uint4*)(g_v1h + (size_t)s * D1 + off);
        float kf[8];
        h8_to_f8(kr, kf);
        float d0 = 0.f;
        #pragma unroll
        for (int q = 0; q < 8; ++q) d0 += qf[q] * kf[q];
        #pragma unroll
        for (int o = 4; o; o >>= 1) d0 += __shfl_xor_sync(0xffffffffu, d0, o);
        float logit = d0 * 0.125f;
        float mn = fmaxf(m, logit);
        float c = __expf(m - mn), pe = __expf(logit - mn);
        l = l * c + pe;
        float vf[8];
        h8_to_f8(vr, vf);
        #pragma unroll
        for (int q = 0; q < 8; ++q) A[q] = A[q] * c + pe * vf[q];
        m = mn;
    }

    float inv = (l > 0.0f) ? 1.0f / l : 0.0f;
    const float* hb = g_h + (size_t)node * D1 + off;
    float4 h0 = *(const float4*)hb;
    float4 h1 = *(const float4*)(hb + 4);
    float hv[8] = { h0.x, h0.y, h0.z, h0.w, h1.x, h1.y, h1.z, h1.w };

    union { uint4 u; __half2 h[4]; } hu;
    #pragma unroll
    for (int j = 0; j < 4; ++j) {
        float v0 = fmaxf(hv[2 * j]     + A[2 * j]     * inv, 0.0f);
        float v1 = fmaxf(hv[2 * j + 1] + A[2 * j + 1] * inv, 0.0f);
        hu.h[j] = __floats2half2_rn(v0, v1);
    }
    *(uint4*)(g_hf + (size_t)node * D1 + off) = hu.u;
}

// ---------------- attention layer 2: 1 head, d=128, warp per node, unroll 4 --
__global__ void attn2_kernel(int n)
{
    int node = (blockIdx.x * blockDim.x + threadIdx.x) >> 5;
    int lane = threadIdx.x & 31;
    if (node >= n) return;

    int base = node * EMB + 4 * lane;
    float4 qv = *(const float4*)(g_q2 + base);

    float m = -1e30f, l = 0.0f;
    float4 A = make_float4(0.f, 0.f, 0.f, 0.f);
    int beg = g_offs[node], end = g_offs[node + 1];
    const float scale = 0.088388347648318447f;   // 1/sqrt(128)

    int p = beg;
    for (; p + 4 <= end; p += 4) {
        uint2 kr[4], vr[4];
        #pragma unroll
        for (int j = 0; j < 4; ++j) {
            int s = g_srcs[p + j];
            kr[j] = *(const uint2*)(g_k2h + (size_t)s * EMB + 4 * lane);
            vr[j] = *(const uint2*)(g_v2h + (size_t)s * EMB + 4 * lane);
        }
        float d[4];
        #pragma unroll
        for (int j = 0; j < 4; ++j) {
            union { uint2 u; __half2 h[2]; } c;
            c.u = kr[j];
            float2 p0 = __half22float2(c.h[0]);
            float2 p1 = __half22float2(c.h[1]);
            d[j] = qv.x * p0.x + qv.y * p0.y + qv.z * p1.x + qv.w * p1.y;
        }
        #pragma unroll
        for (int o = 16; o; o >>= 1)
            #pragma unroll
            for (int j = 0; j < 4; ++j)
                d[j] += __shfl_xor_sync(0xffffffffu, d[j], o);
        #pragma unroll
        for (int j = 0; j < 4; ++j) {
            float logit = d[j] * scale;
            float mn = fmaxf(m, logit);
            float c = __expf(m - mn), pe = __expf(logit - mn);
            l = l * c + pe;
            union { uint2 u; __half2 h[2]; } cv;
            cv.u = vr[j];
            float2 v0 = __half22float2(cv.h[0]);
            float2 v1 = __half22float2(cv.h[1]);
            A.x = A.x * c + pe * v0.x; A.y = A.y * c + pe * v0.y;
            A.z = A.z * c + pe * v1.x; A.w = A.w * c + pe * v1.y;
            m = mn;
        }
    }
    for (; p < end; ++p) {
        int s = g_srcs[p];
        union { uint2 u; __half2 h[2]; } ck, cv;
        ck.u = *(const uint2*)(g_k2h + (size_t)s * EMB + 4 * lane);
        cv.u = *(const uint2*)(g_v2h + (size_t)s * EMB + 4 * lane);
        float2 p0 = __half22float2(ck.h[0]);
        float2 p1 = __half22float2(ck.h[1]);
        float d0 = qv.x * p0.x + qv.y * p0.y + qv.z * p1.x + qv.w * p1.y;
        #pragma unroll
        for (int o = 16; o; o >>= 1) d0 += __shfl_xor_sync(0xffffffffu, d0, o);
        float logit = d0 * scale;
        float mn = fmaxf(m, logit);
        float c = __expf(m - mn), pe = __expf(logit - mn);
        l = l * c + pe;
        float2 v0 = __half22float2(cv.h[0]);
        float2 v1 = __half22float2(cv.h[1]);
        A.x = A.x * c + pe * v0.x; A.y = A.y * c + pe * v0.y;
        A.z = A.z * c + pe * v1.x; A.w = A.w * c + pe * v1.y;
        m = mn;
    }
    if (l > 0.0f) {
        float inv = 1.0f / l;
        float4 o = *(float4*)(g_o2 + base);
        o.x += A.x * inv; o.y += A.y * inv; o.z += A.z * inv; o.w += A.w * inv;
        *(float4*)(g_o2 + base) = o;
    }
}

// ---------------- final mean over nodes (reads g_o2) -------------------------
__global__ void reduce_mean_kernel(float* __restrict__ out, int n) {
    int col = threadIdx.x;   // 128 threads
    float s = 0.0f;
    for (int r = blockIdx.x; r < n; r += gridDim.x)
        s += g_o2[(size_t)r * EMB + col];
    atomicAdd(&out[col], s * (1.0f / (float)n));
}

// ---------------- launch -----------------------------------------------------
extern "C" void kernel_launch(void* const* d_in, const int* in_sizes, int n_in,
                              void* d_out, int out_size)
{
    const float* x  = (const float*)d_in[0];
    const void*  ei = d_in[1];
    const float *Wq1 = (const float*)d_in[2],  *bq1 = (const float*)d_in[3];
    const float *Wk1 = (const float*)d_in[4],  *bk1 = (const float*)d_in[5];
    const float *Wv1 = (const float*)d_in[6],  *bv1 = (const float*)d_in[7];
    const float *Ws1 = (const float*)d_in[8],  *bs1 = (const float*)d_in[9];
    const float *Wq2 = (const float*)d_in[10], *bq2 = (const float*)d_in[11];
    const float *Wk2 = (const float*)d_in[12], *bk2 = (const float*)d_in[13];
    const float *Wv2 = (const float*)d_in[14], *bv2 = (const float*)d_in[15];
    const float *Ws2 = (const float*)d_in[16], *bs2 = (const float*)d_in[17];
    float* out = (float*)d_out;

    const int n = in_sizes[0] / INC;   // 50000
    const int e = in_sizes[1] / 2;     // 800000

    cudaFuncSetAttribute(mma_gemm_kernel,
                         cudaFuncAttributeMaxDynamicSharedMemorySize, GEMM_SMEM_BYTES);

    // ---- init (+dtype detect) + CSR build (by dst) ----
    {
        int threads = 256;
        init_kernel<<<(n + threads - 1) / threads, threads>>>(ei, out, n);
        hist_kernel<<<(e + threads - 1) / threads, threads>>>(ei, e, n);
        int nchunks = (n + 511) / 512;
        scanA_kernel<<<nchunks, 512>>>(n);
        scanB_kernel<<<1, 128>>>(nchunks);
        scanC_kernel<<<(n + threads - 1) / threads, threads>>>(n);
        scatter_kernel<<<(e + threads - 1) / threads, threads>>>(ei, e, n);
    }

    // ---- input conversions ----
    {
        int totx = n * INC;
        xconv_kernel<<<(totx + 255) / 256, 256>>>(x, totx);
        wsplit_kernel<<<1024, 256>>>(Wq1, Wk1, Wv1, Ws1, Wq2, Wk2, Wv2, Ws2);
    }

    int mtiles = (n + 127) / 128;

    // ---- layer 1 projections (q1 fp32, k1/v1 fp16, h fp32) ----
    {
        dim3 grid(8, mtiles);
        mma_gemm_kernel<<<grid, 256, GEMM_SMEM_BYTES>>>(bq1, bk1, bv1, bs1,
                                                        n, INC, 2, 0, 0, 0);
    }

    // ---- layer 1 attention (fused skip+attn+relu -> g_hf fp16) ----
    {
        int blocks = (n + 7) / 8;
        attn1_kernel<<<blocks, 256>>>(n);
    }

    // ---- layer 2 projections (q2 fp32, k2/v2 fp16, o2 fp32) ----
    {
        dim3 grid(4, mtiles);
        mma_gemm_kernel<<<grid, 256, GEMM_SMEM_BYTES>>>(bq2, bk2, bv2, bs2,
                                                        n, D1, 1, 131072, 1, 4);
    }

    // ---- layer 2 attention (adds into g_o2) ----
    {
        int blocks = (n + 7) / 8;
        attn2_kernel<<<blocks, 256>>>(n);
    }

    // ---- final mean over nodes ----
    reduce_mean_kernel<<<256, EMB>>>(out, n);
}